// round 9
// baseline (speedup 1.0000x reference)
#include <cuda_runtime.h>
#include <cuda_bf16.h>
#include <math.h>
#include <cstdint>

#define D_MODEL   1024
#define T_SEQ     2048
#define B_SZ      4
#define N_HEADS   16
#define HEAD_DIM  64
#define M_ROWS    8192
#define QKV_N     3072

// Scratch (no cudaMalloc allowed)
__device__ __nv_bfloat16  g_qkv_hi[(size_t)M_ROWS * QKV_N];
__device__ __nv_bfloat16  g_qkv_lo[(size_t)M_ROWS * QKV_N];
__device__ __nv_bfloat16  g_x_hi[(size_t)M_ROWS * D_MODEL];
__device__ __nv_bfloat16  g_x_lo[(size_t)M_ROWS * D_MODEL];
__device__ __nv_bfloat16  g_wqkv_hi[(size_t)QKV_N * D_MODEL];
__device__ __nv_bfloat16  g_wqkv_lo[(size_t)QKV_N * D_MODEL];
__device__ __nv_bfloat16  g_wout_hi[(size_t)D_MODEL * D_MODEL];
__device__ __nv_bfloat16  g_wout_lo[(size_t)D_MODEL * D_MODEL];
__device__ __nv_bfloat16  g_att_hi[(size_t)M_ROWS * D_MODEL];
__device__ __nv_bfloat16  g_att_lo[(size_t)M_ROWS * D_MODEL];

__device__ __forceinline__ uint32_t smem_u32(const void* p) {
    uint32_t a;
    asm("{ .reg .u64 t; cvta.to.shared.u64 t, %1; cvt.u32.u64 %0, t; }" : "=r"(a) : "l"(p));
    return a;
}
__device__ __forceinline__ void split_bf(float x, __nv_bfloat16& h, __nv_bfloat16& l) {
    h = __float2bfloat16_rn(x);
    l = __float2bfloat16_rn(x - __bfloat162float(h));
}
__device__ __forceinline__ void split2(float a, float b, uint32_t& h, uint32_t& l) {
    __nv_bfloat16 ha, la, hb, lb;
    split_bf(a, ha, la); split_bf(b, hb, lb);
    __nv_bfloat162 hv(ha, hb), lv(la, lb);
    h = *reinterpret_cast<uint32_t*>(&hv);
    l = *reinterpret_cast<uint32_t*>(&lv);
}

#define LDSM4(r, addr) \
    asm volatile("ldmatrix.sync.aligned.m8n8.x4.shared.b16 {%0,%1,%2,%3}, [%4];" \
        : "=r"((r)[0]), "=r"((r)[1]), "=r"((r)[2]), "=r"((r)[3]) : "r"(addr))
#define LDSM4T(r, addr) \
    asm volatile("ldmatrix.sync.aligned.m8n8.x4.trans.shared.b16 {%0,%1,%2,%3}, [%4];" \
        : "=r"((r)[0]), "=r"((r)[1]), "=r"((r)[2]), "=r"((r)[3]) : "r"(addr))

#define MMA_BF16(d, a, b) \
    asm volatile("mma.sync.aligned.m16n8k16.row.col.f32.bf16.bf16.f32 " \
        "{%0,%1,%2,%3}, {%4,%5,%6,%7}, {%8,%9}, {%0,%1,%2,%3};" \
        : "+f"((d)[0]), "+f"((d)[1]), "+f"((d)[2]), "+f"((d)[3]) \
        : "r"((a)[0]), "r"((a)[1]), "r"((a)[2]), "r"((a)[3]), "r"((b)[0]), "r"((b)[1]))

#define CP16(dst, src) \
    asm volatile("cp.async.cg.shared.global [%0], [%1], 16;" :: "r"(dst), "l"(src) : "memory")
#define CP_COMMIT() asm volatile("cp.async.commit_group;" ::: "memory")

// ---------------------------------------------------------------------------
__global__ void split_x_kernel(const float4* __restrict__ x,
                               __nv_bfloat16* __restrict__ hi,
                               __nv_bfloat16* __restrict__ lo, int n4) {
    const int i = blockIdx.x * 256 + threadIdx.x;
    if (i >= n4) return;
    float4 v = x[i];
    uint32_t h0, l0, h1, l1;
    split2(v.x, v.y, h0, l0); split2(v.z, v.w, h1, l1);
    uint32_t* hp = reinterpret_cast<uint32_t*>(hi) + 2 * i;
    uint32_t* lp = reinterpret_cast<uint32_t*>(lo) + 2 * i;
    hp[0] = h0; hp[1] = h1; lp[0] = l0; lp[1] = l1;
}

__global__ void transpose_split(const float* __restrict__ W,
                                __nv_bfloat16* __restrict__ Wth,
                                __nv_bfloat16* __restrict__ Wtl,
                                int Kr, int Nc, int scale_lim, float scale) {
    __shared__ float tile[32][33];
    const int bx = blockIdx.x * 32, by = blockIdx.y * 32;
    const int tx = threadIdx.x, ty = threadIdx.y;
#pragma unroll
    for (int u = 0; u < 32; u += 8)
        tile[ty + u][tx] = W[(size_t)(by + ty + u) * Nc + bx + tx];
    __syncthreads();
#pragma unroll
    for (int u = 0; u < 32; u += 8) {
        const int n = bx + ty + u;
        float v = tile[tx][ty + u];
        if (n < scale_lim) v *= scale;
        __nv_bfloat16 h, l;
        split_bf(v, h, l);
        const size_t o = (size_t)n * Kr + by + tx;
        Wth[o] = h; Wtl[o] = l;
    }
}

// ---------------------------------------------------------------------------
// 3-MMA split-bf16 GEMM. CTA 128x128, 256 threads, 8 warps of 64x32.
// K-panel 32, 2-stage cp.async pipeline. m_off = row-block offset for
// batch-pipelined launches.
// ---------------------------------------------------------------------------
#define PANEL    32
#define RSTRIDE  80
#define TILE_B   (128 * RSTRIDE)        // 10240
#define STAGE_B  (4 * TILE_B)           // 40960 (Ah, Al, Bh, Bl)

__global__ __launch_bounds__(256, 2) void bf16_gemm(const __nv_bfloat16* __restrict__ Ah,
                                                    const __nv_bfloat16* __restrict__ Al,
                                                    const __nv_bfloat16* __restrict__ Bh,
                                                    const __nv_bfloat16* __restrict__ Bl,
                                                    float* __restrict__ C,
                                                    __nv_bfloat16* __restrict__ Chi,
                                                    __nv_bfloat16* __restrict__ Clo,
                                                    int M, int N, int K, int m_off) {
    extern __shared__ char sm[];
    const uint32_t base = smem_u32(sm);

    const int t = threadIdx.x;
    const int wid = t >> 5, lane = t & 31;
    const int m0 = (blockIdx.y + m_off) * 128, n0 = blockIdx.x * 128;
    const int wm = (wid >> 2) * 64, wn = (wid & 3) * 32;
    const int NKI = K / PANEL;

    const int rg = t >> 2, sg = t & 3;
    const uint32_t s_off = (uint32_t)(rg * RSTRIDE + sg * 16);

#define LOAD_STAGE(i, s) do { \
        const size_t _k0 = (size_t)(i) * PANEL + sg * 8; \
        const uint32_t _st = base + (s) * STAGE_B + s_off; \
        _Pragma("unroll") \
        for (int _u = 0; _u < 2; ++_u) { \
            const int _r = rg + _u * 64; \
            const uint32_t _so = _st + _u * 64 * RSTRIDE; \
            CP16(_so,              Ah + (size_t)(m0 + _r) * K + _k0); \
            CP16(_so + TILE_B,     Al + (size_t)(m0 + _r) * K + _k0); \
            CP16(_so + 2 * TILE_B, Bh + (size_t)(n0 + _r) * K + _k0); \
            CP16(_so + 3 * TILE_B, Bl + (size_t)(n0 + _r) * K + _k0); \
        } \
        CP_COMMIT(); \
    } while (0)

    uint32_t aoff[4], boff[2];
#pragma unroll
    for (int mt = 0; mt < 4; ++mt)
        aoff[mt] = (uint32_t)((wm + mt * 16 + (lane & 15)) * RSTRIDE + (lane >> 4) * 16);
#pragma unroll
    for (int p = 0; p < 2; ++p)
        boff[p] = (uint32_t)((wn + p * 16 + ((lane >> 4) << 3) + (lane & 7)) * RSTRIDE
                             + ((lane >> 3) & 1) * 16);

    float acc[4][4][4];
#pragma unroll
    for (int i = 0; i < 4; ++i)
#pragma unroll
        for (int j = 0; j < 4; ++j)
#pragma unroll
            for (int r = 0; r < 4; ++r) acc[i][j][r] = 0.0f;

    LOAD_STAGE(0, 0);

    for (int i = 0; i < NKI; ++i) {
        if (i + 1 < NKI) {
            LOAD_STAGE(i + 1, (i + 1) & 1);
            asm volatile("cp.async.wait_group 1;" ::: "memory");
        } else {
            asm volatile("cp.async.wait_group 0;" ::: "memory");
        }
        __syncthreads();

        const uint32_t sAh = base + (i & 1) * STAGE_B;
        const uint32_t sAl = sAh + TILE_B;
        const uint32_t sBh = sAh + 2 * TILE_B;
        const uint32_t sBl = sAh + 3 * TILE_B;

#pragma unroll
        for (int ks = 0; ks < 2; ++ks) {
            uint32_t ah[4][4], al[4][4];
#pragma unroll
            for (int mt = 0; mt < 4; ++mt) {
                LDSM4(ah[mt], sAh + aoff[mt] + ks * 32);
                LDSM4(al[mt], sAl + aoff[mt] + ks * 32);
            }
#pragma unroll
            for (int p = 0; p < 2; ++p) {
                uint32_t bh[4], bl[4];
                LDSM4(bh, sBh + boff[p] + ks * 32);
                LDSM4(bl, sBl + boff[p] + ks * 32);
#pragma unroll
                for (int j = 0; j < 2; ++j)
#pragma unroll
                    for (int mt = 0; mt < 4; ++mt)
                        MMA_BF16(acc[mt][2 * p + j], ah[mt], &bh[j * 2]);
#pragma unroll
                for (int j = 0; j < 2; ++j)
#pragma unroll
                    for (int mt = 0; mt < 4; ++mt)
                        MMA_BF16(acc[mt][2 * p + j], ah[mt], &bl[j * 2]);
#pragma unroll
                for (int j = 0; j < 2; ++j)
#pragma unroll
                    for (int mt = 0; mt < 4; ++mt)
                        MMA_BF16(acc[mt][2 * p + j], al[mt], &bh[j * 2]);
            }
        }
        __syncthreads();
    }

    const int r_lo = lane >> 2, c_lo = (lane & 3) * 2;
#pragma unroll
    for (int mt = 0; mt < 4; ++mt) {
        const int row = m0 + wm + mt * 16 + r_lo;
#pragma unroll
        for (int n8 = 0; n8 < 4; ++n8) {
            const int col = n0 + wn + n8 * 8 + c_lo;
            if (C) {
                *(float2*)(C + (size_t)row * N + col) =
                    make_float2(acc[mt][n8][0], acc[mt][n8][1]);
                *(float2*)(C + (size_t)(row + 8) * N + col) =
                    make_float2(acc[mt][n8][2], acc[mt][n8][3]);
            } else {
                uint32_t h, l;
                split2(acc[mt][n8][0], acc[mt][n8][1], h, l);
                *(uint32_t*)(Chi + (size_t)row * N + col) = h;
                *(uint32_t*)(Clo + (size_t)row * N + col) = l;
                split2(acc[mt][n8][2], acc[mt][n8][3], h, l);
                *(uint32_t*)(Chi + (size_t)(row + 8) * N + col) = h;
                *(uint32_t*)(Clo + (size_t)(row + 8) * N + col) = l;
            }
        }
    }
#undef LOAD_STAGE
}

// ---------------------------------------------------------------------------
// Tensor-core flash attention (causal, split bf16, 3-MMA, exp2 softmax).
// Per-batch launch: grid (16 qtiles, 16 heads), batch index passed in.
// ---------------------------------------------------------------------------
#define FAS    144
#define FTILE  (128 * FAS)
#define KVST   (4 * FTILE)

__global__ __launch_bounds__(256, 1) void flash_attn_tc(
    const __nv_bfloat16* __restrict__ qkvh,
    const __nv_bfloat16* __restrict__ qkvl,
    __nv_bfloat16* __restrict__ att_hi,
    __nv_bfloat16* __restrict__ att_lo,
    int batch) {
    extern __shared__ char sm[];
    const uint32_t base  = smem_u32(sm);
    const uint32_t qbase = base + 2 * KVST;

    const int qi = (int)gridDim.x - 1 - (int)blockIdx.x;   // big tiles first
    const int b  = batch;
    const int h  = blockIdx.y;
    const int t  = threadIdx.x;
    const int wid = t >> 5, lane = t & 31;

    const int rowQ0 = b * T_SEQ + qi * 128;
    const int colQ = h * HEAD_DIM;
    const int colK = D_MODEL + h * HEAD_DIM;
    const int colV = 2 * D_MODEL + h * HEAD_DIM;

    const int rg = t >> 3, sg = t & 7;
    const uint32_t ls_off = (uint32_t)(rg * FAS + sg * 16);

#define LOADKV(kt, s) do { \
        const uint32_t _st = base + (s) * KVST + ls_off; \
        _Pragma("unroll") \
        for (int _u = 0; _u < 4; ++_u) { \
            const int _r = rg + _u * 32; \
            const size_t _row = (size_t)(b * T_SEQ + (kt) * 128 + _r) * QKV_N; \
            const uint32_t _so = _st + _u * 32 * FAS; \
            CP16(_so,             qkvh + _row + colK + sg * 8); \
            CP16(_so + FTILE,     qkvl + _row + colK + sg * 8); \
            CP16(_so + 2 * FTILE, qkvh + _row + colV + sg * 8); \
            CP16(_so + 3 * FTILE, qkvl + _row + colV + sg * 8); \
        } \
        CP_COMMIT(); \
    } while (0)

    {
#pragma unroll
        for (int u = 0; u < 4; ++u) {
            const int r = rg + u * 32;
            const size_t row = (size_t)(rowQ0 + r) * QKV_N;
            const uint32_t so = qbase + ls_off + u * 32 * FAS;
            CP16(so,         qkvh + row + colQ + sg * 8);
            CP16(so + FTILE, qkvl + row + colQ + sg * 8);
        }
        CP_COMMIT();
    }
    LOADKV(0, 0);

    asm volatile("cp.async.wait_group 1;" ::: "memory");
    __syncthreads();

    uint32_t qh[4][4], ql[4][4];
    {
        const uint32_t aoff = (uint32_t)((wid * 16 + (lane & 15)) * FAS + (lane >> 4) * 16);
#pragma unroll
        for (int ks = 0; ks < 4; ++ks) {
            LDSM4(qh[ks], qbase + aoff + ks * 32);
            LDSM4(ql[ks], qbase + FTILE + aoff + ks * 32);
        }
    }

    uint32_t koff[8];
#pragma unroll
    for (int p = 0; p < 8; ++p)
        koff[p] = (uint32_t)((p * 16 + ((lane >> 4) << 3) + (lane & 7)) * FAS
                             + ((lane >> 3) & 1) * 16);
    const int vg = lane >> 3;
    const uint32_t voff_r = (uint32_t)(((vg & 1) * 8 + (lane & 7)) * FAS + (vg >> 1) * 16);

    float O[8][4];
#pragma unroll
    for (int j = 0; j < 8; ++j)
#pragma unroll
        for (int r = 0; r < 4; ++r) O[j][r] = 0.0f;
    float m0 = -1e30f, m1 = -1e30f, l0 = 0.0f, l1 = 0.0f;

    const int r_lo = lane >> 2, c_lo = (lane & 3) * 2;
    const int row_loc0 = wid * 16 + r_lo;
    const int row_loc1 = row_loc0 + 8;

    for (int kt = 0; kt <= qi; ++kt) {
        if (kt + 1 <= qi) {
            LOADKV(kt + 1, (kt + 1) & 1);
            asm volatile("cp.async.wait_group 1;" ::: "memory");
        } else {
            asm volatile("cp.async.wait_group 0;" ::: "memory");
        }
        __syncthreads();

        const uint32_t sKh = base + (kt & 1) * KVST;
        const uint32_t sKl = sKh + FTILE;
        const uint32_t sVh = sKh + 2 * FTILE;
        const uint32_t sVl = sKh + 3 * FTILE;

        float s[16][4];
#pragma unroll
        for (int j = 0; j < 16; ++j)
#pragma unroll
            for (int r = 0; r < 4; ++r) s[j][r] = 0.0f;

#pragma unroll
        for (int ks = 0; ks < 4; ++ks) {
#pragma unroll
            for (int pp = 0; pp < 4; ++pp) {
                uint32_t kbh[2][4], kbl[2][4];
                LDSM4(kbh[0], sKh + koff[2 * pp]     + ks * 32);
                LDSM4(kbl[0], sKl + koff[2 * pp]     + ks * 32);
                LDSM4(kbh[1], sKh + koff[2 * pp + 1] + ks * 32);
                LDSM4(kbl[1], sKl + koff[2 * pp + 1] + ks * 32);
#pragma unroll
                for (int q = 0; q < 2; ++q)
#pragma unroll
                    for (int j = 0; j < 2; ++j)
                        MMA_BF16(s[2 * (2 * pp + q) + j], qh[ks], &kbh[q][j * 2]);
#pragma unroll
                for (int q = 0; q < 2; ++q)
#pragma unroll
                    for (int j = 0; j < 2; ++j)
                        MMA_BF16(s[2 * (2 * pp + q) + j], qh[ks], &kbl[q][j * 2]);
#pragma unroll
                for (int q = 0; q < 2; ++q)
#pragma unroll
                    for (int j = 0; j < 2; ++j)
                        MMA_BF16(s[2 * (2 * pp + q) + j], ql[ks], &kbh[q][j * 2]);
            }
        }

        if (kt == qi) {
#pragma unroll
            for (int n8 = 0; n8 < 16; ++n8) {
                const int c0 = n8 * 8 + c_lo;
                if (c0 > row_loc0)     s[n8][0] = -1e30f;
                if (c0 + 1 > row_loc0) s[n8][1] = -1e30f;
                if (c0 > row_loc1)     s[n8][2] = -1e30f;
                if (c0 + 1 > row_loc1) s[n8][3] = -1e30f;
            }
        }

        float mx0 = -1e30f, mx1 = -1e30f;
#pragma unroll
        for (int j = 0; j < 16; ++j) {
            mx0 = fmaxf(mx0, fmaxf(s[j][0], s[j][1]));
            mx1 = fmaxf(mx1, fmaxf(s[j][2], s[j][3]));
        }
#pragma unroll
        for (int off = 1; off <= 2; off <<= 1) {
            mx0 = fmaxf(mx0, __shfl_xor_sync(0xffffffffu, mx0, off, 32));
            mx1 = fmaxf(mx1, __shfl_xor_sync(0xffffffffu, mx1, off, 32));
        }
        const float mn0 = fmaxf(m0, mx0), mn1 = fmaxf(m1, mx1);
        const float cr0 = exp2f(m0 - mn0), cr1 = exp2f(m1 - mn1);
        float sum0 = 0.0f, sum1 = 0.0f;
#pragma unroll
        for (int j = 0; j < 16; ++j) {
            s[j][0] = exp2f(s[j][0] - mn0); sum0 += s[j][0];
            s[j][1] = exp2f(s[j][1] - mn0); sum0 += s[j][1];
            s[j][2] = exp2f(s[j][2] - mn1); sum1 += s[j][2];
            s[j][3] = exp2f(s[j][3] - mn1); sum1 += s[j][3];
        }
#pragma unroll
        for (int off = 1; off <= 2; off <<= 1) {
            sum0 += __shfl_xor_sync(0xffffffffu, sum0, off, 32);
            sum1 += __shfl_xor_sync(0xffffffffu, sum1, off, 32);
        }
        l0 = l0 * cr0 + sum0; l1 = l1 * cr1 + sum1;
        m0 = mn0; m1 = mn1;
#pragma unroll
        for (int j = 0; j < 8; ++j) {
            O[j][0] *= cr0; O[j][1] *= cr0; O[j][2] *= cr1; O[j][3] *= cr1;
        }

#pragma unroll
        for (int ks2 = 0; ks2 < 8; ++ks2) {
            uint32_t afh[4], afl[4];
            split2(s[2 * ks2][0],     s[2 * ks2][1],     afh[0], afl[0]);
            split2(s[2 * ks2][2],     s[2 * ks2][3],     afh[1], afl[1]);
            split2(s[2 * ks2 + 1][0], s[2 * ks2 + 1][1], afh[2], afl[2]);
            split2(s[2 * ks2 + 1][2], s[2 * ks2 + 1][3], afh[3], afl[3]);
            const uint32_t vrow = voff_r + ks2 * 16 * FAS;
#pragma unroll
            for (int jj = 0; jj < 2; ++jj) {
                uint32_t vbh[2][4], vbl[2][4];
                LDSM4T(vbh[0], sVh + vrow + (2 * jj) * 32);
                LDSM4T(vbl[0], sVl + vrow + (2 * jj) * 32);
                LDSM4T(vbh[1], sVh + vrow + (2 * jj + 1) * 32);
                LDSM4T(vbl[1], sVl + vrow + (2 * jj + 1) * 32);
#pragma unroll
                for (int q = 0; q < 2; ++q)
#pragma unroll
                    for (int j = 0; j < 2; ++j)
                        MMA_BF16(O[2 * (2 * jj + q) + j], afh, &vbh[q][j * 2]);
#pragma unroll
                for (int q = 0; q < 2; ++q)
#pragma unroll
                    for (int j = 0; j < 2; ++j)
                        MMA_BF16(O[2 * (2 * jj + q) + j], afh, &vbl[q][j * 2]);
#pragma unroll
                for (int q = 0; q < 2; ++q)
#pragma unroll
                    for (int j = 0; j < 2; ++j)
                        MMA_BF16(O[2 * (2 * jj + q) + j], afl, &vbh[q][j * 2]);
            }
        }
        __syncthreads();
    }

    const float inv0 = 1.0f / l0, inv1 = 1.0f / l1;
    const int grow0 = rowQ0 + row_loc0;
    const int grow1 = rowQ0 + row_loc1;
#pragma unroll
    for (int n8 = 0; n8 < 8; ++n8) {
        const int col = h * HEAD_DIM + n8 * 8 + c_lo;
        uint32_t hh, ll;
        split2(O[n8][0] * inv0, O[n8][1] * inv0, hh, ll);
        *(uint32_t*)(att_hi + (size_t)grow0 * D_MODEL + col) = hh;
        *(uint32_t*)(att_lo + (size_t)grow0 * D_MODEL + col) = ll;
        split2(O[n8][2] * inv1, O[n8][3] * inv1, hh, ll);
        *(uint32_t*)(att_hi + (size_t)grow1 * D_MODEL + col) = hh;
        *(uint32_t*)(att_lo + (size_t)grow1 * D_MODEL + col) = ll;
    }
#undef LOADKV
}

// ---------------------------------------------------------------------------
// Batch-pipelined orchestration: s0 = prep + G1 chunks, s2 = attention chunks,
// s3 = out-projection chunks. Events encode the per-batch dependency chain.
// All stream/event objects are created on the (uncaptured) correctness call
// and reused; graph capture sees only launches, event records and waits.
// ---------------------------------------------------------------------------
extern "C" void kernel_launch(void* const* d_in, const int* in_sizes, int n_in,
                              void* d_out, int out_size) {
    const float* x     = (const float*)d_in[0];
    const float* W_qkv = (const float*)d_in[1];
    const float* W_out = (const float*)d_in[2];
    float*       out   = (float*)d_out;

    __nv_bfloat16 *qh, *ql2, *xh, *xl, *wqh, *wql, *woh, *wol, *ath, *atl;
    cudaGetSymbolAddress((void**)&qh,  g_qkv_hi);
    cudaGetSymbolAddress((void**)&ql2, g_qkv_lo);
    cudaGetSymbolAddress((void**)&xh,  g_x_hi);
    cudaGetSymbolAddress((void**)&xl,  g_x_lo);
    cudaGetSymbolAddress((void**)&wqh, g_wqkv_hi);
    cudaGetSymbolAddress((void**)&wql, g_wqkv_lo);
    cudaGetSymbolAddress((void**)&woh, g_wout_hi);
    cudaGetSymbolAddress((void**)&wol, g_wout_lo);
    cudaGetSymbolAddress((void**)&ath, g_att_hi);
    cudaGetSymbolAddress((void**)&atl, g_att_lo);

    static cudaStream_t s2 = nullptr, s3 = nullptr;
    static cudaEvent_t evFork, evG1[B_SZ], evA[B_SZ], evG3;
    if (s2 == nullptr) {
        cudaStreamCreateWithFlags(&s2, cudaStreamNonBlocking);
        cudaStreamCreateWithFlags(&s3, cudaStreamNonBlocking);
        cudaEventCreateWithFlags(&evFork, cudaEventDisableTiming);
        cudaEventCreateWithFlags(&evG3, cudaEventDisableTiming);
        for (int b = 0; b < B_SZ; ++b) {
            cudaEventCreateWithFlags(&evG1[b], cudaEventDisableTiming);
            cudaEventCreateWithFlags(&evA[b], cudaEventDisableTiming);
        }
    }

    const int smem_gemm = 2 * STAGE_B;                 // 81920
    const int smem_attn = 2 * KVST + 2 * FTILE;        // 184320
    cudaFuncSetAttribute(bf16_gemm, cudaFuncAttributeMaxDynamicSharedMemorySize, smem_gemm);
    cudaFuncSetAttribute(flash_attn_tc, cudaFuncAttributeMaxDynamicSharedMemorySize, smem_attn);

    const float qscale = 0.125f * 1.4426950408889634f;  // fold log2(e) for exp2 softmax

    // fork s2/s3 from the capture-origin stream
    cudaEventRecord(evFork, 0);
    cudaStreamWaitEvent(s2, evFork, 0);
    cudaStreamWaitEvent(s3, evFork, 0);

    // prep: W_out transpose off the critical path (s2); x-split + W_qkv on s0
    transpose_split<<<dim3(D_MODEL / 32, D_MODEL / 32), dim3(32, 8), 0, s2>>>(
        W_out, woh, wol, D_MODEL, D_MODEL, 0, 1.0f);
    split_x_kernel<<<(M_ROWS * D_MODEL / 4 + 255) / 256, 256>>>(
        (const float4*)x, xh, xl, M_ROWS * D_MODEL / 4);
    transpose_split<<<dim3(QKV_N / 32, D_MODEL / 32), dim3(32, 8)>>>(
        W_qkv, wqh, wql, D_MODEL, QKV_N, D_MODEL, qscale);

    // s0: per-batch QKV GEMM chunks
    for (int b = 0; b < B_SZ; ++b) {
        bf16_gemm<<<dim3(QKV_N / 128, 16), 256, smem_gemm>>>(
            xh, xl, wqh, wql, nullptr, qh, ql2, M_ROWS, QKV_N, D_MODEL, b * 16);
        cudaEventRecord(evG1[b], 0);
    }

    // s2: per-batch attention (after its qkv chunk; after W_out tr by stream order)
    for (int b = 0; b < B_SZ; ++b) {
        cudaStreamWaitEvent(s2, evG1[b], 0);
        flash_attn_tc<<<dim3(T_SEQ / 128, N_HEADS), 256, smem_attn, s2>>>(
            qh, ql2, ath, atl, b);
        cudaEventRecord(evA[b], s2);
    }

    // s3: per-batch out-projection (after its attention chunk)
    for (int b = 0; b < B_SZ; ++b) {
        cudaStreamWaitEvent(s3, evA[b], 0);
        bf16_gemm<<<dim3(D_MODEL / 128, 16), 256, smem_gemm, s3>>>(
            ath, atl, woh, wol, out, nullptr, nullptr, M_ROWS, D_MODEL, D_MODEL, b * 16);
    }
    cudaEventRecord(evG3, s3);

    // join everything back to the origin stream
    cudaStreamWaitEvent(0, evG3, 0);
}

// round 10
// speedup vs baseline: 1.2228x; 1.2228x over previous
#include <cuda_runtime.h>
#include <cuda_bf16.h>
#include <cuda_fp16.h>
#include <math.h>
#include <cstdint>

#define D_MODEL   1024
#define T_SEQ     2048
#define B_SZ      4
#define N_HEADS   16
#define HEAD_DIM  64
#define M_ROWS    8192
#define QKV_N     3072

// Scratch (no cudaMalloc allowed)
__device__ __nv_bfloat16  g_qkv_hi[(size_t)M_ROWS * QKV_N];   // attention inputs (bf16 split)
__device__ __nv_bfloat16  g_qkv_lo[(size_t)M_ROWS * QKV_N];
__device__ __half         g_x_h[(size_t)M_ROWS * D_MODEL];    // GEMM activations (fp16 split)
__device__ __half         g_x_l[(size_t)M_ROWS * D_MODEL];
__device__ __half         g_att_h[(size_t)M_ROWS * D_MODEL];
__device__ __half         g_att_l[(size_t)M_ROWS * D_MODEL];
__device__ __half         g_wqkv_h[(size_t)QKV_N * D_MODEL];  // weights (single fp16, transposed)
__device__ __half         g_wout_h[(size_t)D_MODEL * D_MODEL];

__device__ __forceinline__ uint32_t smem_u32(const void* p) {
    uint32_t a;
    asm("{ .reg .u64 t; cvta.to.shared.u64 t, %1; cvt.u32.u64 %0, t; }" : "=r"(a) : "l"(p));
    return a;
}
// bf16 split (attention path, unchanged)
__device__ __forceinline__ void split_bf(float x, __nv_bfloat16& h, __nv_bfloat16& l) {
    h = __float2bfloat16_rn(x);
    l = __float2bfloat16_rn(x - __bfloat162float(h));
}
__device__ __forceinline__ void split2(float a, float b, uint32_t& h, uint32_t& l) {
    __nv_bfloat16 ha, la, hb, lb;
    split_bf(a, ha, la); split_bf(b, hb, lb);
    __nv_bfloat162 hv(ha, hb), lv(la, lb);
    h = *reinterpret_cast<uint32_t*>(&hv);
    l = *reinterpret_cast<uint32_t*>(&lv);
}
// fp16 split (GEMM activation path)
__device__ __forceinline__ void split2h(float a, float b, uint32_t& h, uint32_t& l) {
    __half ha = __float2half_rn(a), hb = __float2half_rn(b);
    __half la = __float2half_rn(a - __half2float(ha));
    __half lb = __float2half_rn(b - __half2float(hb));
    __half2 hv = __halves2half2(ha, hb), lv = __halves2half2(la, lb);
    h = *reinterpret_cast<uint32_t*>(&hv);
    l = *reinterpret_cast<uint32_t*>(&lv);
}

#define LDSM4(r, addr) \
    asm volatile("ldmatrix.sync.aligned.m8n8.x4.shared.b16 {%0,%1,%2,%3}, [%4];" \
        : "=r"((r)[0]), "=r"((r)[1]), "=r"((r)[2]), "=r"((r)[3]) : "r"(addr))
#define LDSM4T(r, addr) \
    asm volatile("ldmatrix.sync.aligned.m8n8.x4.trans.shared.b16 {%0,%1,%2,%3}, [%4];" \
        : "=r"((r)[0]), "=r"((r)[1]), "=r"((r)[2]), "=r"((r)[3]) : "r"(addr))

#define MMA_BF16(d, a, b) \
    asm volatile("mma.sync.aligned.m16n8k16.row.col.f32.bf16.bf16.f32 " \
        "{%0,%1,%2,%3}, {%4,%5,%6,%7}, {%8,%9}, {%0,%1,%2,%3};" \
        : "+f"((d)[0]), "+f"((d)[1]), "+f"((d)[2]), "+f"((d)[3]) \
        : "r"((a)[0]), "r"((a)[1]), "r"((a)[2]), "r"((a)[3]), "r"((b)[0]), "r"((b)[1]))

#define MMA_F16(d, a, b) \
    asm volatile("mma.sync.aligned.m16n8k16.row.col.f32.f16.f16.f32 " \
        "{%0,%1,%2,%3}, {%4,%5,%6,%7}, {%8,%9}, {%0,%1,%2,%3};" \
        : "+f"((d)[0]), "+f"((d)[1]), "+f"((d)[2]), "+f"((d)[3]) \
        : "r"((a)[0]), "r"((a)[1]), "r"((a)[2]), "r"((a)[3]), "r"((b)[0]), "r"((b)[1]))

#define CP16(dst, src) \
    asm volatile("cp.async.cg.shared.global [%0], [%1], 16;" :: "r"(dst), "l"(src) : "memory")
#define CP_COMMIT() asm volatile("cp.async.commit_group;" ::: "memory")

// ---------------------------------------------------------------------------
// x (fp32) -> fp16 hi/lo split
// ---------------------------------------------------------------------------
__global__ void split_x_f16(const float4* __restrict__ x,
                            __half* __restrict__ hi,
                            __half* __restrict__ lo, int n4) {
    const int i = blockIdx.x * 256 + threadIdx.x;
    if (i >= n4) return;
    float4 v = x[i];
    uint32_t h0, l0, h1, l1;
    split2h(v.x, v.y, h0, l0); split2h(v.z, v.w, h1, l1);
    uint32_t* hp = reinterpret_cast<uint32_t*>(hi) + 2 * i;
    uint32_t* lp = reinterpret_cast<uint32_t*>(lo) + 2 * i;
    hp[0] = h0; hp[1] = h1; lp[0] = l0; lp[1] = l1;
}

// transpose + round to single fp16 (+optional scale on first scale_lim rows)
__global__ void transpose_f16(const float* __restrict__ W,
                              __half* __restrict__ Wt,
                              int Kr, int Nc, int scale_lim, float scale) {
    __shared__ float tile[32][33];
    const int bx = blockIdx.x * 32, by = blockIdx.y * 32;
    const int tx = threadIdx.x, ty = threadIdx.y;
#pragma unroll
    for (int u = 0; u < 32; u += 8)
        tile[ty + u][tx] = W[(size_t)(by + ty + u) * Nc + bx + tx];
    __syncthreads();
#pragma unroll
    for (int u = 0; u < 32; u += 8) {
        const int n = bx + ty + u;
        float v = tile[tx][ty + u];
        if (n < scale_lim) v *= scale;
        Wt[(size_t)n * Kr + by + tx] = __float2half_rn(v);
    }
}

// ---------------------------------------------------------------------------
// 2-term split-fp16 GEMM: C = (Ah+Al) @ B^T, B = RN_fp16(W) single.
// CTA 128x128, 256 threads, 8 warps 64x32; K-panel 32, 2-stage cp.async.
// ---------------------------------------------------------------------------
#define PANEL    32
#define RSTRIDE  80
#define TILE_B   (128 * RSTRIDE)        // 10240
#define SSTAGE   (3 * TILE_B)           // 30720 (Ah, Al, B)

__global__ __launch_bounds__(256, 2) void f16_gemm(const __half* __restrict__ Ah,
                                                   const __half* __restrict__ Al,
                                                   const __half* __restrict__ B,
                                                   float* __restrict__ C,
                                                   __nv_bfloat16* __restrict__ Chi,
                                                   __nv_bfloat16* __restrict__ Clo,
                                                   int M, int N, int K) {
    extern __shared__ char sm[];
    const uint32_t base = smem_u32(sm);

    const int t = threadIdx.x;
    const int wid = t >> 5, lane = t & 31;
    const int m0 = blockIdx.y * 128, n0 = blockIdx.x * 128;
    const int wm = (wid >> 2) * 64, wn = (wid & 3) * 32;
    const int NKI = K / PANEL;

    const int rg = t >> 2, sg = t & 3;
    const uint32_t s_off = (uint32_t)(rg * RSTRIDE + sg * 16);

#define LOAD_STAGE(i, s) do { \
        const size_t _k0 = (size_t)(i) * PANEL + sg * 8; \
        const uint32_t _st = base + (s) * SSTAGE + s_off; \
        _Pragma("unroll") \
        for (int _u = 0; _u < 2; ++_u) { \
            const int _r = rg + _u * 64; \
            const uint32_t _so = _st + _u * 64 * RSTRIDE; \
            CP16(_so,              Ah + (size_t)(m0 + _r) * K + _k0); \
            CP16(_so + TILE_B,     Al + (size_t)(m0 + _r) * K + _k0); \
            CP16(_so + 2 * TILE_B, B  + (size_t)(n0 + _r) * K + _k0); \
        } \
        CP_COMMIT(); \
    } while (0)

    uint32_t aoff[4], boff[2];
#pragma unroll
    for (int mt = 0; mt < 4; ++mt)
        aoff[mt] = (uint32_t)((wm + mt * 16 + (lane & 15)) * RSTRIDE + (lane >> 4) * 16);
#pragma unroll
    for (int p = 0; p < 2; ++p)
        boff[p] = (uint32_t)((wn + p * 16 + ((lane >> 4) << 3) + (lane & 7)) * RSTRIDE
                             + ((lane >> 3) & 1) * 16);

    float acc[4][4][4];
#pragma unroll
    for (int i = 0; i < 4; ++i)
#pragma unroll
        for (int j = 0; j < 4; ++j)
#pragma unroll
            for (int r = 0; r < 4; ++r) acc[i][j][r] = 0.0f;

    LOAD_STAGE(0, 0);

    for (int i = 0; i < NKI; ++i) {
        if (i + 1 < NKI) {
            LOAD_STAGE(i + 1, (i + 1) & 1);
            asm volatile("cp.async.wait_group 1;" ::: "memory");
        } else {
            asm volatile("cp.async.wait_group 0;" ::: "memory");
        }
        __syncthreads();

        const uint32_t sAh = base + (i & 1) * SSTAGE;
        const uint32_t sAl = sAh + TILE_B;
        const uint32_t sB  = sAh + 2 * TILE_B;

#pragma unroll
        for (int ks = 0; ks < 2; ++ks) {
            uint32_t ah[4][4], al[4][4];
#pragma unroll
            for (int mt = 0; mt < 4; ++mt) {
                LDSM4(ah[mt], sAh + aoff[mt] + ks * 32);
                LDSM4(al[mt], sAl + aoff[mt] + ks * 32);
            }
#pragma unroll
            for (int p = 0; p < 2; ++p) {
                uint32_t bf[4];
                LDSM4(bf, sB + boff[p] + ks * 32);
#pragma unroll
                for (int j = 0; j < 2; ++j) {
#pragma unroll
                    for (int mt = 0; mt < 4; ++mt) {
                        MMA_F16(acc[mt][2 * p + j], ah[mt], &bf[j * 2]);
                        MMA_F16(acc[mt][2 * p + j], al[mt], &bf[j * 2]);
                    }
                }
            }
        }
        __syncthreads();
    }

    const int r_lo = lane >> 2, c_lo = (lane & 3) * 2;
#pragma unroll
    for (int mt = 0; mt < 4; ++mt) {
        const int row = m0 + wm + mt * 16 + r_lo;
#pragma unroll
        for (int n8 = 0; n8 < 4; ++n8) {
            const int col = n0 + wn + n8 * 8 + c_lo;
            if (C) {
                *(float2*)(C + (size_t)row * N + col) =
                    make_float2(acc[mt][n8][0], acc[mt][n8][1]);
                *(float2*)(C + (size_t)(row + 8) * N + col) =
                    make_float2(acc[mt][n8][2], acc[mt][n8][3]);
            } else {
                uint32_t h, l;
                split2(acc[mt][n8][0], acc[mt][n8][1], h, l);
                *(uint32_t*)(Chi + (size_t)row * N + col) = h;
                *(uint32_t*)(Clo + (size_t)row * N + col) = l;
                split2(acc[mt][n8][2], acc[mt][n8][3], h, l);
                *(uint32_t*)(Chi + (size_t)(row + 8) * N + col) = h;
                *(uint32_t*)(Clo + (size_t)(row + 8) * N + col) = l;
            }
        }
    }
#undef LOAD_STAGE
}

// ---------------------------------------------------------------------------
// Tensor-core flash attention (causal, split bf16, 3-MMA, exp2 softmax).
// Internals unchanged from the 907us config; epilogue emits fp16 hi/lo.
// ---------------------------------------------------------------------------
#define FAS    144
#define FTILE  (128 * FAS)
#define KVST   (4 * FTILE)

__global__ __launch_bounds__(256, 1) void flash_attn_tc(
    const __nv_bfloat16* __restrict__ qkvh,
    const __nv_bfloat16* __restrict__ qkvl,
    __half* __restrict__ att_h,
    __half* __restrict__ att_l) {
    extern __shared__ char sm[];
    const uint32_t base  = smem_u32(sm);
    const uint32_t qbase = base + 2 * KVST;

    const int qi = (int)gridDim.x - 1 - (int)blockIdx.x;
    const int bh = blockIdx.y;
    const int b  = bh >> 4, h = bh & 15;
    const int t  = threadIdx.x;
    const int wid = t >> 5, lane = t & 31;

    const int rowQ0 = b * T_SEQ + qi * 128;
    const int colQ = h * HEAD_DIM;
    const int colK = D_MODEL + h * HEAD_DIM;
    const int colV = 2 * D_MODEL + h * HEAD_DIM;

    const int rg = t >> 3, sg = t & 7;
    const uint32_t ls_off = (uint32_t)(rg * FAS + sg * 16);

#define LOADKV(kt, s) do { \
        const uint32_t _st = base + (s) * KVST + ls_off; \
        _Pragma("unroll") \
        for (int _u = 0; _u < 4; ++_u) { \
            const int _r = rg + _u * 32; \
            const size_t _row = (size_t)(b * T_SEQ + (kt) * 128 + _r) * QKV_N; \
            const uint32_t _so = _st + _u * 32 * FAS; \
            CP16(_so,             qkvh + _row + colK + sg * 8); \
            CP16(_so + FTILE,     qkvl + _row + colK + sg * 8); \
            CP16(_so + 2 * FTILE, qkvh + _row + colV + sg * 8); \
            CP16(_so + 3 * FTILE, qkvl + _row + colV + sg * 8); \
        } \
        CP_COMMIT(); \
    } while (0)

    {
#pragma unroll
        for (int u = 0; u < 4; ++u) {
            const int r = rg + u * 32;
            const size_t row = (size_t)(rowQ0 + r) * QKV_N;
            const uint32_t so = qbase + ls_off + u * 32 * FAS;
            CP16(so,         qkvh + row + colQ + sg * 8);
            CP16(so + FTILE, qkvl + row + colQ + sg * 8);
        }
        CP_COMMIT();
    }
    LOADKV(0, 0);

    asm volatile("cp.async.wait_group 1;" ::: "memory");
    __syncthreads();

    uint32_t qh[4][4], ql[4][4];
    {
        const uint32_t aoff = (uint32_t)((wid * 16 + (lane & 15)) * FAS + (lane >> 4) * 16);
#pragma unroll
        for (int ks = 0; ks < 4; ++ks) {
            LDSM4(qh[ks], qbase + aoff + ks * 32);
            LDSM4(ql[ks], qbase + FTILE + aoff + ks * 32);
        }
    }

    uint32_t koff[8];
#pragma unroll
    for (int p = 0; p < 8; ++p)
        koff[p] = (uint32_t)((p * 16 + ((lane >> 4) << 3) + (lane & 7)) * FAS
                             + ((lane >> 3) & 1) * 16);
    const int vg = lane >> 3;
    const uint32_t voff_r = (uint32_t)(((vg & 1) * 8 + (lane & 7)) * FAS + (vg >> 1) * 16);

    float O[8][4];
#pragma unroll
    for (int j = 0; j < 8; ++j)
#pragma unroll
        for (int r = 0; r < 4; ++r) O[j][r] = 0.0f;
    float m0 = -1e30f, m1 = -1e30f, l0 = 0.0f, l1 = 0.0f;

    const int r_lo = lane >> 2, c_lo = (lane & 3) * 2;
    const int row_loc0 = wid * 16 + r_lo;
    const int row_loc1 = row_loc0 + 8;

    for (int kt = 0; kt <= qi; ++kt) {
        if (kt + 1 <= qi) {
            LOADKV(kt + 1, (kt + 1) & 1);
            asm volatile("cp.async.wait_group 1;" ::: "memory");
        } else {
            asm volatile("cp.async.wait_group 0;" ::: "memory");
        }
        __syncthreads();

        const uint32_t sKh = base + (kt & 1) * KVST;
        const uint32_t sKl = sKh + FTILE;
        const uint32_t sVh = sKh + 2 * FTILE;
        const uint32_t sVl = sKh + 3 * FTILE;

        float s[16][4];
#pragma unroll
        for (int j = 0; j < 16; ++j)
#pragma unroll
            for (int r = 0; r < 4; ++r) s[j][r] = 0.0f;

#pragma unroll
        for (int ks = 0; ks < 4; ++ks) {
#pragma unroll
            for (int p = 0; p < 8; ++p) {
                uint32_t kbh[4], kbl[4];
                LDSM4(kbh, sKh + koff[p] + ks * 32);
                LDSM4(kbl, sKl + koff[p] + ks * 32);
#pragma unroll
                for (int j = 0; j < 2; ++j) {
                    const int n8 = 2 * p + j;
                    MMA_BF16(s[n8], qh[ks], &kbh[j * 2]);
                    MMA_BF16(s[n8], qh[ks], &kbl[j * 2]);
                    MMA_BF16(s[n8], ql[ks], &kbh[j * 2]);
                }
            }
        }

        if (kt == qi) {
#pragma unroll
            for (int n8 = 0; n8 < 16; ++n8) {
                const int c0 = n8 * 8 + c_lo;
                if (c0 > row_loc0)     s[n8][0] = -1e30f;
                if (c0 + 1 > row_loc0) s[n8][1] = -1e30f;
                if (c0 > row_loc1)     s[n8][2] = -1e30f;
                if (c0 + 1 > row_loc1) s[n8][3] = -1e30f;
            }
        }

        float mx0 = -1e30f, mx1 = -1e30f;
#pragma unroll
        for (int j = 0; j < 16; ++j) {
            mx0 = fmaxf(mx0, fmaxf(s[j][0], s[j][1]));
            mx1 = fmaxf(mx1, fmaxf(s[j][2], s[j][3]));
        }
#pragma unroll
        for (int off = 1; off <= 2; off <<= 1) {
            mx0 = fmaxf(mx0, __shfl_xor_sync(0xffffffffu, mx0, off, 32));
            mx1 = fmaxf(mx1, __shfl_xor_sync(0xffffffffu, mx1, off, 32));
        }
        const float mn0 = fmaxf(m0, mx0), mn1 = fmaxf(m1, mx1);
        const float cr0 = exp2f(m0 - mn0), cr1 = exp2f(m1 - mn1);
        float sum0 = 0.0f, sum1 = 0.0f;
#pragma unroll
        for (int j = 0; j < 16; ++j) {
            s[j][0] = exp2f(s[j][0] - mn0); sum0 += s[j][0];
            s[j][1] = exp2f(s[j][1] - mn0); sum0 += s[j][1];
            s[j][2] = exp2f(s[j][2] - mn1); sum1 += s[j][2];
            s[j][3] = exp2f(s[j][3] - mn1); sum1 += s[j][3];
        }
#pragma unroll
        for (int off = 1; off <= 2; off <<= 1) {
            sum0 += __shfl_xor_sync(0xffffffffu, sum0, off, 32);
            sum1 += __shfl_xor_sync(0xffffffffu, sum1, off, 32);
        }
        l0 = l0 * cr0 + sum0; l1 = l1 * cr1 + sum1;
        m0 = mn0; m1 = mn1;
#pragma unroll
        for (int j = 0; j < 8; ++j) {
            O[j][0] *= cr0; O[j][1] *= cr0; O[j][2] *= cr1; O[j][3] *= cr1;
        }

#pragma unroll
        for (int ks2 = 0; ks2 < 8; ++ks2) {
            uint32_t afh[4], afl[4];
            split2(s[2 * ks2][0],     s[2 * ks2][1],     afh[0], afl[0]);
            split2(s[2 * ks2][2],     s[2 * ks2][3],     afh[1], afl[1]);
            split2(s[2 * ks2 + 1][0], s[2 * ks2 + 1][1], afh[2], afl[2]);
            split2(s[2 * ks2 + 1][2], s[2 * ks2 + 1][3], afh[3], afl[3]);
            const uint32_t vrow = voff_r + ks2 * 16 * FAS;
#pragma unroll
            for (int j2 = 0; j2 < 4; ++j2) {
                uint32_t vbh[4], vbl[4];
                LDSM4T(vbh, sVh + vrow + j2 * 32);
                LDSM4T(vbl, sVl + vrow + j2 * 32);
#pragma unroll
                for (int j = 0; j < 2; ++j) {
                    const int n8 = 2 * j2 + j;
                    MMA_BF16(O[n8], afh, &vbh[j * 2]);
                    MMA_BF16(O[n8], afh, &vbl[j * 2]);
                    MMA_BF16(O[n8], afl, &vbh[j * 2]);
                }
            }
        }
        __syncthreads();
    }

    // epilogue: normalize, split to fp16 hi/lo for the projection GEMM
    const float inv0 = 1.0f / l0, inv1 = 1.0f / l1;
    const int grow0 = rowQ0 + row_loc0;
    const int grow1 = rowQ0 + row_loc1;
#pragma unroll
    for (int n8 = 0; n8 < 8; ++n8) {
        const int col = h * HEAD_DIM + n8 * 8 + c_lo;
        uint32_t hh, ll;
        split2h(O[n8][0] * inv0, O[n8][1] * inv0, hh, ll);
        *(uint32_t*)(att_h + (size_t)grow0 * D_MODEL + col) = hh;
        *(uint32_t*)(att_l + (size_t)grow0 * D_MODEL + col) = ll;
        split2h(O[n8][2] * inv1, O[n8][3] * inv1, hh, ll);
        *(uint32_t*)(att_h + (size_t)grow1 * D_MODEL + col) = hh;
        *(uint32_t*)(att_l + (size_t)grow1 * D_MODEL + col) = ll;
    }
#undef LOADKV
}

// ---------------------------------------------------------------------------
extern "C" void kernel_launch(void* const* d_in, const int* in_sizes, int n_in,
                              void* d_out, int out_size) {
    const float* x     = (const float*)d_in[0];
    const float* W_qkv = (const float*)d_in[1];
    const float* W_out = (const float*)d_in[2];
    float*       out   = (float*)d_out;

    __nv_bfloat16 *qh, *ql2;
    __half *xh, *xl, *wq, *wo, *ath, *atl;
    cudaGetSymbolAddress((void**)&qh,  g_qkv_hi);
    cudaGetSymbolAddress((void**)&ql2, g_qkv_lo);
    cudaGetSymbolAddress((void**)&xh,  g_x_h);
    cudaGetSymbolAddress((void**)&xl,  g_x_l);
    cudaGetSymbolAddress((void**)&wq,  g_wqkv_h);
    cudaGetSymbolAddress((void**)&wo,  g_wout_h);
    cudaGetSymbolAddress((void**)&ath, g_att_h);
    cudaGetSymbolAddress((void**)&atl, g_att_l);

    const int smem_gemm = 2 * SSTAGE;                  // 61440
    const int smem_attn = 2 * KVST + 2 * FTILE;        // 184320
    cudaFuncSetAttribute(f16_gemm, cudaFuncAttributeMaxDynamicSharedMemorySize, smem_gemm);
    cudaFuncSetAttribute(flash_attn_tc, cudaFuncAttributeMaxDynamicSharedMemorySize, smem_attn);

    const float qscale = 0.125f * 1.4426950408889634f;  // fold log2(e) for exp2 softmax
    split_x_f16<<<(M_ROWS * D_MODEL / 4 + 255) / 256, 256>>>(
        (const float4*)x, xh, xl, M_ROWS * D_MODEL / 4);
    transpose_f16<<<dim3(QKV_N / 32, D_MODEL / 32), dim3(32, 8)>>>(
        W_qkv, wq, D_MODEL, QKV_N, D_MODEL, qscale);
    transpose_f16<<<dim3(D_MODEL / 32, D_MODEL / 32), dim3(32, 8)>>>(
        W_out, wo, D_MODEL, D_MODEL, 0, 1.0f);

    // 1) qkv = x @ W_qkv  (fp16 2-term; split bf16 output for attention)
    f16_gemm<<<dim3(QKV_N / 128, M_ROWS / 128), 256, smem_gemm>>>(
        xh, xl, wq, nullptr, qh, ql2, M_ROWS, QKV_N, D_MODEL);

    // 2) causal flash attention (bf16 3-term internals; fp16 hi/lo output)
    flash_attn_tc<<<dim3(T_SEQ / 128, B_SZ * N_HEADS), 256, smem_attn>>>(
        qh, ql2, ath, atl);

    // 3) out = att @ W_out  (fp16 2-term; fp32 output)
    f16_gemm<<<dim3(D_MODEL / 128, M_ROWS / 128), 256, smem_gemm>>>(
        ath, atl, wo, out, nullptr, nullptr, M_ROWS, D_MODEL, D_MODEL);
}

// round 11
// speedup vs baseline: 1.3938x; 1.1399x over previous
#include <cuda_runtime.h>
#include <cuda_bf16.h>
#include <cuda_fp16.h>
#include <math.h>
#include <cstdint>

#define D_MODEL   1024
#define T_SEQ     2048
#define B_SZ      4
#define N_HEADS   16
#define HEAD_DIM  64
#define M_ROWS    8192
#define QKV_N     3072

// Scratch (no cudaMalloc allowed) — all fp16 split pairs
__device__ __half  g_qkv_h[(size_t)M_ROWS * QKV_N];
__device__ __half  g_qkv_l[(size_t)M_ROWS * QKV_N];
__device__ __half  g_x_h[(size_t)M_ROWS * D_MODEL];
__device__ __half  g_x_l[(size_t)M_ROWS * D_MODEL];
__device__ __half  g_att_h[(size_t)M_ROWS * D_MODEL];
__device__ __half  g_att_l[(size_t)M_ROWS * D_MODEL];
__device__ __half  g_wqkv_h[(size_t)QKV_N * D_MODEL];
__device__ __half  g_wout_h[(size_t)D_MODEL * D_MODEL];

__device__ __forceinline__ uint32_t smem_u32(const void* p) {
    uint32_t a;
    asm("{ .reg .u64 t; cvta.to.shared.u64 t, %1; cvt.u32.u64 %0, t; }" : "=r"(a) : "l"(p));
    return a;
}
// fp16 hi/lo split of a float pair -> packed half2 words
__device__ __forceinline__ void split2h(float a, float b, uint32_t& h, uint32_t& l) {
    __half ha = __float2half_rn(a), hb = __float2half_rn(b);
    __half la = __float2half_rn(a - __half2float(ha));
    __half lb = __float2half_rn(b - __half2float(hb));
    __half2 hv = __halves2half2(ha, hb), lv = __halves2half2(la, lb);
    h = *reinterpret_cast<uint32_t*>(&hv);
    l = *reinterpret_cast<uint32_t*>(&lv);
}

#define LDSM4(r, addr) \
    asm volatile("ldmatrix.sync.aligned.m8n8.x4.shared.b16 {%0,%1,%2,%3}, [%4];" \
        : "=r"((r)[0]), "=r"((r)[1]), "=r"((r)[2]), "=r"((r)[3]) : "r"(addr))
#define LDSM4T(r, addr) \
    asm volatile("ldmatrix.sync.aligned.m8n8.x4.trans.shared.b16 {%0,%1,%2,%3}, [%4];" \
        : "=r"((r)[0]), "=r"((r)[1]), "=r"((r)[2]), "=r"((r)[3]) : "r"(addr))

#define MMA_F16(d, a, b) \
    asm volatile("mma.sync.aligned.m16n8k16.row.col.f32.f16.f16.f32 " \
        "{%0,%1,%2,%3}, {%4,%5,%6,%7}, {%8,%9}, {%0,%1,%2,%3};" \
        : "+f"((d)[0]), "+f"((d)[1]), "+f"((d)[2]), "+f"((d)[3]) \
        : "r"((a)[0]), "r"((a)[1]), "r"((a)[2]), "r"((a)[3]), "r"((b)[0]), "r"((b)[1]))

#define CP16(dst, src) \
    asm volatile("cp.async.cg.shared.global [%0], [%1], 16;" :: "r"(dst), "l"(src) : "memory")
#define CP_COMMIT() asm volatile("cp.async.commit_group;" ::: "memory")

// ---------------------------------------------------------------------------
__global__ void split_x_f16(const float4* __restrict__ x,
                            __half* __restrict__ hi,
                            __half* __restrict__ lo, int n4) {
    const int i = blockIdx.x * 256 + threadIdx.x;
    if (i >= n4) return;
    float4 v = x[i];
    uint32_t h0, l0, h1, l1;
    split2h(v.x, v.y, h0, l0); split2h(v.z, v.w, h1, l1);
    uint32_t* hp = reinterpret_cast<uint32_t*>(hi) + 2 * i;
    uint32_t* lp = reinterpret_cast<uint32_t*>(lo) + 2 * i;
    hp[0] = h0; hp[1] = h1; lp[0] = l0; lp[1] = l1;
}

__global__ void transpose_f16(const float* __restrict__ W,
                              __half* __restrict__ Wt,
                              int Kr, int Nc, int scale_lim, float scale) {
    __shared__ float tile[32][33];
    const int bx = blockIdx.x * 32, by = blockIdx.y * 32;
    const int tx = threadIdx.x, ty = threadIdx.y;
#pragma unroll
    for (int u = 0; u < 32; u += 8)
        tile[ty + u][tx] = W[(size_t)(by + ty + u) * Nc + bx + tx];
    __syncthreads();
#pragma unroll
    for (int u = 0; u < 32; u += 8) {
        const int n = bx + ty + u;
        float v = tile[tx][ty + u];
        if (n < scale_lim) v *= scale;
        Wt[(size_t)n * Kr + by + tx] = __float2half_rn(v);
    }
}

// ---------------------------------------------------------------------------
// 2-term split-fp16 GEMM: C = (Ah+Al) @ B^T, B = RN_fp16(W).
// CTA 128x128, 256 threads, 8 warps 64x32; K-panel 32, 2-stage cp.async.
// ---------------------------------------------------------------------------
#define PANEL    32
#define RSTRIDE  80
#define TILE_B   (128 * RSTRIDE)        // 10240
#define SSTAGE   (3 * TILE_B)           // 30720 (Ah, Al, B)

__global__ __launch_bounds__(256, 2) void f16_gemm(const __half* __restrict__ Ah,
                                                   const __half* __restrict__ Al,
                                                   const __half* __restrict__ B,
                                                   float* __restrict__ C,
                                                   __half* __restrict__ Chi,
                                                   __half* __restrict__ Clo,
                                                   int M, int N, int K) {
    extern __shared__ char sm[];
    const uint32_t base = smem_u32(sm);

    const int t = threadIdx.x;
    const int wid = t >> 5, lane = t & 31;
    const int m0 = blockIdx.y * 128, n0 = blockIdx.x * 128;
    const int wm = (wid >> 2) * 64, wn = (wid & 3) * 32;
    const int NKI = K / PANEL;

    const int rg = t >> 2, sg = t & 3;
    const uint32_t s_off = (uint32_t)(rg * RSTRIDE + sg * 16);

#define LOAD_STAGE(i, s) do { \
        const size_t _k0 = (size_t)(i) * PANEL + sg * 8; \
        const uint32_t _st = base + (s) * SSTAGE + s_off; \
        _Pragma("unroll") \
        for (int _u = 0; _u < 2; ++_u) { \
            const int _r = rg + _u * 64; \
            const uint32_t _so = _st + _u * 64 * RSTRIDE; \
            CP16(_so,              Ah + (size_t)(m0 + _r) * K + _k0); \
            CP16(_so + TILE_B,     Al + (size_t)(m0 + _r) * K + _k0); \
            CP16(_so + 2 * TILE_B, B  + (size_t)(n0 + _r) * K + _k0); \
        } \
        CP_COMMIT(); \
    } while (0)

    uint32_t aoff[4], boff[2];
#pragma unroll
    for (int mt = 0; mt < 4; ++mt)
        aoff[mt] = (uint32_t)((wm + mt * 16 + (lane & 15)) * RSTRIDE + (lane >> 4) * 16);
#pragma unroll
    for (int p = 0; p < 2; ++p)
        boff[p] = (uint32_t)((wn + p * 16 + ((lane >> 4) << 3) + (lane & 7)) * RSTRIDE
                             + ((lane >> 3) & 1) * 16);

    float acc[4][4][4];
#pragma unroll
    for (int i = 0; i < 4; ++i)
#pragma unroll
        for (int j = 0; j < 4; ++j)
#pragma unroll
            for (int r = 0; r < 4; ++r) acc[i][j][r] = 0.0f;

    LOAD_STAGE(0, 0);

    for (int i = 0; i < NKI; ++i) {
        if (i + 1 < NKI) {
            LOAD_STAGE(i + 1, (i + 1) & 1);
            asm volatile("cp.async.wait_group 1;" ::: "memory");
        } else {
            asm volatile("cp.async.wait_group 0;" ::: "memory");
        }
        __syncthreads();

        const uint32_t sAh = base + (i & 1) * SSTAGE;
        const uint32_t sAl = sAh + TILE_B;
        const uint32_t sB  = sAh + 2 * TILE_B;

#pragma unroll
        for (int ks = 0; ks < 2; ++ks) {
            uint32_t ah[4][4], al[4][4];
#pragma unroll
            for (int mt = 0; mt < 4; ++mt) {
                LDSM4(ah[mt], sAh + aoff[mt] + ks * 32);
                LDSM4(al[mt], sAl + aoff[mt] + ks * 32);
            }
#pragma unroll
            for (int p = 0; p < 2; ++p) {
                uint32_t bf[4];
                LDSM4(bf, sB + boff[p] + ks * 32);
#pragma unroll
                for (int j = 0; j < 2; ++j) {
#pragma unroll
                    for (int mt = 0; mt < 4; ++mt) {
                        MMA_F16(acc[mt][2 * p + j], ah[mt], &bf[j * 2]);
                        MMA_F16(acc[mt][2 * p + j], al[mt], &bf[j * 2]);
                    }
                }
            }
        }
        __syncthreads();
    }

    const int r_lo = lane >> 2, c_lo = (lane & 3) * 2;
#pragma unroll
    for (int mt = 0; mt < 4; ++mt) {
        const int row = m0 + wm + mt * 16 + r_lo;
#pragma unroll
        for (int n8 = 0; n8 < 4; ++n8) {
            const int col = n0 + wn + n8 * 8 + c_lo;
            if (C) {
                *(float2*)(C + (size_t)row * N + col) =
                    make_float2(acc[mt][n8][0], acc[mt][n8][1]);
                *(float2*)(C + (size_t)(row + 8) * N + col) =
                    make_float2(acc[mt][n8][2], acc[mt][n8][3]);
            } else {
                uint32_t h, l;
                split2h(acc[mt][n8][0], acc[mt][n8][1], h, l);
                *(uint32_t*)(Chi + (size_t)row * N + col) = h;
                *(uint32_t*)(Clo + (size_t)row * N + col) = l;
                split2h(acc[mt][n8][2], acc[mt][n8][3], h, l);
                *(uint32_t*)(Chi + (size_t)(row + 8) * N + col) = h;
                *(uint32_t*)(Clo + (size_t)(row + 8) * N + col) = l;
            }
        }
    }
#undef LOAD_STAGE
}

// ---------------------------------------------------------------------------
// Tensor-core flash attention, fp16 2-term:
//   S = (Qh+Ql) K^T  with K = fp16 hi only;  O += (Ph+Pl) V with V = hi only.
// 256 thr / 8 warps; 128q x 128k tiles; double-buffered K/V (2 tiles/stage).
// ---------------------------------------------------------------------------
#define FAS    144
#define FTILE  (128 * FAS)
#define KVST   (2 * FTILE)              // Kh, Vh per stage

__global__ __launch_bounds__(256, 1) void flash_attn_tc(
    const __half* __restrict__ qkvh,
    const __half* __restrict__ qkvl,
    __half* __restrict__ att_h,
    __half* __restrict__ att_l) {
    extern __shared__ char sm[];
    const uint32_t base  = smem_u32(sm);
    const uint32_t qbase = base + 2 * KVST;

    const int qi = (int)gridDim.x - 1 - (int)blockIdx.x;
    const int bh = blockIdx.y;
    const int b  = bh >> 4, h = bh & 15;
    const int t  = threadIdx.x;
    const int wid = t >> 5, lane = t & 31;

    const int rowQ0 = b * T_SEQ + qi * 128;
    const int colQ = h * HEAD_DIM;
    const int colK = D_MODEL + h * HEAD_DIM;
    const int colV = 2 * D_MODEL + h * HEAD_DIM;

    const int rg = t >> 3, sg = t & 7;
    const uint32_t ls_off = (uint32_t)(rg * FAS + sg * 16);

#define LOADKV(kt, s) do { \
        const uint32_t _st = base + (s) * KVST + ls_off; \
        _Pragma("unroll") \
        for (int _u = 0; _u < 4; ++_u) { \
            const int _r = rg + _u * 32; \
            const size_t _row = (size_t)(b * T_SEQ + (kt) * 128 + _r) * QKV_N; \
            const uint32_t _so = _st + _u * 32 * FAS; \
            CP16(_so,         qkvh + _row + colK + sg * 8); \
            CP16(_so + FTILE, qkvh + _row + colV + sg * 8); \
        } \
        CP_COMMIT(); \
    } while (0)

    {
#pragma unroll
        for (int u = 0; u < 4; ++u) {
            const int r = rg + u * 32;
            const size_t row = (size_t)(rowQ0 + r) * QKV_N;
            const uint32_t so = qbase + ls_off + u * 32 * FAS;
            CP16(so,         qkvh + row + colQ + sg * 8);
            CP16(so + FTILE, qkvl + row + colQ + sg * 8);
        }
        CP_COMMIT();
    }
    LOADKV(0, 0);

    asm volatile("cp.async.wait_group 1;" ::: "memory");
    __syncthreads();

    uint32_t qh[4][4], ql[4][4];
    {
        const uint32_t aoff = (uint32_t)((wid * 16 + (lane & 15)) * FAS + (lane >> 4) * 16);
#pragma unroll
        for (int ks = 0; ks < 4; ++ks) {
            LDSM4(qh[ks], qbase + aoff + ks * 32);
            LDSM4(ql[ks], qbase + FTILE + aoff + ks * 32);
        }
    }

    uint32_t koff[8];
#pragma unroll
    for (int p = 0; p < 8; ++p)
        koff[p] = (uint32_t)((p * 16 + ((lane >> 4) << 3) + (lane & 7)) * FAS
                             + ((lane >> 3) & 1) * 16);
    const int vg = lane >> 3;
    const uint32_t voff_r = (uint32_t)(((vg & 1) * 8 + (lane & 7)) * FAS + (vg >> 1) * 16);

    float O[8][4];
#pragma unroll
    for (int j = 0; j < 8; ++j)
#pragma unroll
        for (int r = 0; r < 4; ++r) O[j][r] = 0.0f;
    float m0 = -1e30f, m1 = -1e30f, l0 = 0.0f, l1 = 0.0f;

    const int r_lo = lane >> 2, c_lo = (lane & 3) * 2;
    const int row_loc0 = wid * 16 + r_lo;
    const int row_loc1 = row_loc0 + 8;

    for (int kt = 0; kt <= qi; ++kt) {
        if (kt + 1 <= qi) {
            LOADKV(kt + 1, (kt + 1) & 1);
            asm volatile("cp.async.wait_group 1;" ::: "memory");
        } else {
            asm volatile("cp.async.wait_group 0;" ::: "memory");
        }
        __syncthreads();

        const uint32_t sK = base + (kt & 1) * KVST;
        const uint32_t sV = sK + FTILE;

        // ---- S = (Qh+Ql) K^T, K single fp16
        float s[16][4];
#pragma unroll
        for (int j = 0; j < 16; ++j)
#pragma unroll
            for (int r = 0; r < 4; ++r) s[j][r] = 0.0f;

#pragma unroll
        for (int ks = 0; ks < 4; ++ks) {
#pragma unroll
            for (int p = 0; p < 8; ++p) {
                uint32_t kb[4];
                LDSM4(kb, sK + koff[p] + ks * 32);
#pragma unroll
                for (int j = 0; j < 2; ++j) {
                    const int n8 = 2 * p + j;
                    MMA_F16(s[n8], qh[ks], &kb[j * 2]);
                    MMA_F16(s[n8], ql[ks], &kb[j * 2]);
                }
            }
        }

        if (kt == qi) {
#pragma unroll
            for (int n8 = 0; n8 < 16; ++n8) {
                const int c0 = n8 * 8 + c_lo;
                if (c0 > row_loc0)     s[n8][0] = -1e30f;
                if (c0 + 1 > row_loc0) s[n8][1] = -1e30f;
                if (c0 > row_loc1)     s[n8][2] = -1e30f;
                if (c0 + 1 > row_loc1) s[n8][3] = -1e30f;
            }
        }

        float mx0 = -1e30f, mx1 = -1e30f;
#pragma unroll
        for (int j = 0; j < 16; ++j) {
            mx0 = fmaxf(mx0, fmaxf(s[j][0], s[j][1]));
            mx1 = fmaxf(mx1, fmaxf(s[j][2], s[j][3]));
        }
#pragma unroll
        for (int off = 1; off <= 2; off <<= 1) {
            mx0 = fmaxf(mx0, __shfl_xor_sync(0xffffffffu, mx0, off, 32));
            mx1 = fmaxf(mx1, __shfl_xor_sync(0xffffffffu, mx1, off, 32));
        }
        const float mn0 = fmaxf(m0, mx0), mn1 = fmaxf(m1, mx1);
        const float cr0 = exp2f(m0 - mn0), cr1 = exp2f(m1 - mn1);
        float sum0 = 0.0f, sum1 = 0.0f;
#pragma unroll
        for (int j = 0; j < 16; ++j) {
            s[j][0] = exp2f(s[j][0] - mn0); sum0 += s[j][0];
            s[j][1] = exp2f(s[j][1] - mn0); sum0 += s[j][1];
            s[j][2] = exp2f(s[j][2] - mn1); sum1 += s[j][2];
            s[j][3] = exp2f(s[j][3] - mn1); sum1 += s[j][3];
        }
#pragma unroll
        for (int off = 1; off <= 2; off <<= 1) {
            sum0 += __shfl_xor_sync(0xffffffffu, sum0, off, 32);
            sum1 += __shfl_xor_sync(0xffffffffu, sum1, off, 32);
        }
        l0 = l0 * cr0 + sum0; l1 = l1 * cr1 + sum1;
        m0 = mn0; m1 = mn1;
#pragma unroll
        for (int j = 0; j < 8; ++j) {
            O[j][0] *= cr0; O[j][1] *= cr0; O[j][2] *= cr1; O[j][3] *= cr1;
        }

        // ---- O += (Ph+Pl) V, V single fp16
#pragma unroll
        for (int ks2 = 0; ks2 < 8; ++ks2) {
            uint32_t afh[4], afl[4];
            split2h(s[2 * ks2][0],     s[2 * ks2][1],     afh[0], afl[0]);
            split2h(s[2 * ks2][2],     s[2 * ks2][3],     afh[1], afl[1]);
            split2h(s[2 * ks2 + 1][0], s[2 * ks2 + 1][1], afh[2], afl[2]);
            split2h(s[2 * ks2 + 1][2], s[2 * ks2 + 1][3], afh[3], afl[3]);
            const uint32_t vrow = voff_r + ks2 * 16 * FAS;
#pragma unroll
            for (int j2 = 0; j2 < 4; ++j2) {
                uint32_t vb[4];
                LDSM4T(vb, sV + vrow + j2 * 32);
#pragma unroll
                for (int j = 0; j < 2; ++j) {
                    const int n8 = 2 * j2 + j;
                    MMA_F16(O[n8], afh, &vb[j * 2]);
                    MMA_F16(O[n8], afl, &vb[j * 2]);
                }
            }
        }
        __syncthreads();
    }

    // epilogue: normalize, split to fp16 hi/lo for the projection GEMM
    const float inv0 = 1.0f / l0, inv1 = 1.0f / l1;
    const int grow0 = rowQ0 + row_loc0;
    const int grow1 = rowQ0 + row_loc1;
#pragma unroll
    for (int n8 = 0; n8 < 8; ++n8) {
        const int col = h * HEAD_DIM + n8 * 8 + c_lo;
        uint32_t hh, ll;
        split2h(O[n8][0] * inv0, O[n8][1] * inv0, hh, ll);
        *(uint32_t*)(att_h + (size_t)grow0 * D_MODEL + col) = hh;
        *(uint32_t*)(att_l + (size_t)grow0 * D_MODEL + col) = ll;
        split2h(O[n8][2] * inv1, O[n8][3] * inv1, hh, ll);
        *(uint32_t*)(att_h + (size_t)grow1 * D_MODEL + col) = hh;
        *(uint32_t*)(att_l + (size_t)grow1 * D_MODEL + col) = ll;
    }
#undef LOADKV
}

// ---------------------------------------------------------------------------
extern "C" void kernel_launch(void* const* d_in, const int* in_sizes, int n_in,
                              void* d_out, int out_size) {
    const float* x     = (const float*)d_in[0];
    const float* W_qkv = (const float*)d_in[1];
    const float* W_out = (const float*)d_in[2];
    float*       out   = (float*)d_out;

    __half *qh, *ql2, *xh, *xl, *wq, *wo, *ath, *atl;
    cudaGetSymbolAddress((void**)&qh,  g_qkv_h);
    cudaGetSymbolAddress((void**)&ql2, g_qkv_l);
    cudaGetSymbolAddress((void**)&xh,  g_x_h);
    cudaGetSymbolAddress((void**)&xl,  g_x_l);
    cudaGetSymbolAddress((void**)&wq,  g_wqkv_h);
    cudaGetSymbolAddress((void**)&wo,  g_wout_h);
    cudaGetSymbolAddress((void**)&ath, g_att_h);
    cudaGetSymbolAddress((void**)&atl, g_att_l);

    const int smem_gemm = 2 * SSTAGE;                  // 61440
    const int smem_attn = 2 * KVST + 2 * FTILE;        // 110592
    cudaFuncSetAttribute(f16_gemm, cudaFuncAttributeMaxDynamicSharedMemorySize, smem_gemm);
    cudaFuncSetAttribute(flash_attn_tc, cudaFuncAttributeMaxDynamicSharedMemorySize, smem_attn);

    const float qscale = 0.125f * 1.4426950408889634f;  // fold log2(e) for exp2 softmax
    split_x_f16<<<(M_ROWS * D_MODEL / 4 + 255) / 256, 256>>>(
        (const float4*)x, xh, xl, M_ROWS * D_MODEL / 4);
    transpose_f16<<<dim3(QKV_N / 32, D_MODEL / 32), dim3(32, 8)>>>(
        W_qkv, wq, D_MODEL, QKV_N, D_MODEL, qscale);
    transpose_f16<<<dim3(D_MODEL / 32, D_MODEL / 32), dim3(32, 8)>>>(
        W_out, wo, D_MODEL, D_MODEL, 0, 1.0f);

    // 1) qkv = x @ W_qkv  (fp16 2-term; fp16 hi/lo output)
    f16_gemm<<<dim3(QKV_N / 128, M_ROWS / 128), 256, smem_gemm>>>(
        xh, xl, wq, nullptr, qh, ql2, M_ROWS, QKV_N, D_MODEL);

    // 2) causal flash attention (fp16 2-term internals; fp16 hi/lo output)
    flash_attn_tc<<<dim3(T_SEQ / 128, B_SZ * N_HEADS), 256, smem_attn>>>(
        qh, ql2, ath, atl);

    // 3) out = att @ W_out  (fp16 2-term; fp32 output)
    f16_gemm<<<dim3(D_MODEL / 128, M_ROWS / 128), 256, smem_gemm>>>(
        ath, atl, wo, out, nullptr, nullptr, M_ROWS, D_MODEL, D_MODEL);
}

// round 12
// speedup vs baseline: 1.5070x; 1.0812x over previous
#include <cuda_runtime.h>
#include <cuda_fp16.h>
#include <math.h>
#include <cstdint>

#define D_MODEL   1024
#define T_SEQ     2048
#define B_SZ      4
#define N_HEADS   16
#define HEAD_DIM  64
#define M_ROWS    8192
#define QKV_N     3072

// Scratch (no cudaMalloc allowed) — fp16 split pairs
__device__ __half  g_qkv_h[(size_t)M_ROWS * QKV_N];
__device__ __half  g_qkv_l[(size_t)M_ROWS * QKV_N];
__device__ __half  g_x_h[(size_t)M_ROWS * D_MODEL];
__device__ __half  g_x_l[(size_t)M_ROWS * D_MODEL];
__device__ __half  g_att_h[(size_t)M_ROWS * D_MODEL];
__device__ __half  g_att_l[(size_t)M_ROWS * D_MODEL];
__device__ __half  g_wqkv_h[(size_t)QKV_N * D_MODEL];
__device__ __half  g_wout_h[(size_t)D_MODEL * D_MODEL];

__device__ __forceinline__ uint32_t smem_u32(const void* p) {
    uint32_t a;
    asm("{ .reg .u64 t; cvta.to.shared.u64 t, %1; cvt.u32.u64 %0, t; }" : "=r"(a) : "l"(p));
    return a;
}
__device__ __forceinline__ void split2h(float a, float b, uint32_t& h, uint32_t& l) {
    __half ha = __float2half_rn(a), hb = __float2half_rn(b);
    __half la = __float2half_rn(a - __half2float(ha));
    __half lb = __float2half_rn(b - __half2float(hb));
    __half2 hv = __halves2half2(ha, hb), lv = __halves2half2(la, lb);
    h = *reinterpret_cast<uint32_t*>(&hv);
    l = *reinterpret_cast<uint32_t*>(&lv);
}

#define LDSM4(r, addr) \
    asm volatile("ldmatrix.sync.aligned.m8n8.x4.shared.b16 {%0,%1,%2,%3}, [%4];" \
        : "=r"((r)[0]), "=r"((r)[1]), "=r"((r)[2]), "=r"((r)[3]) : "r"(addr))
#define LDSM4T(r, addr) \
    asm volatile("ldmatrix.sync.aligned.m8n8.x4.trans.shared.b16 {%0,%1,%2,%3}, [%4];" \
        : "=r"((r)[0]), "=r"((r)[1]), "=r"((r)[2]), "=r"((r)[3]) : "r"(addr))

#define MMA_F16(d, a, b) \
    asm volatile("mma.sync.aligned.m16n8k16.row.col.f32.f16.f16.f32 " \
        "{%0,%1,%2,%3}, {%4,%5,%6,%7}, {%8,%9}, {%0,%1,%2,%3};" \
        : "+f"((d)[0]), "+f"((d)[1]), "+f"((d)[2]), "+f"((d)[3]) \
        : "r"((a)[0]), "r"((a)[1]), "r"((a)[2]), "r"((a)[3]), "r"((b)[0]), "r"((b)[1]))

#define CP16(dst, src) \
    asm volatile("cp.async.cg.shared.global [%0], [%1], 16;" :: "r"(dst), "l"(src) : "memory")
#define CP_COMMIT() asm volatile("cp.async.commit_group;" ::: "memory")

// ---------------------------------------------------------------------------
__global__ void split_x_f16(const float4* __restrict__ x,
                            __half* __restrict__ hi,
                            __half* __restrict__ lo, int n4) {
    const int i = blockIdx.x * 256 + threadIdx.x;
    if (i >= n4) return;
    float4 v = x[i];
    uint32_t h0, l0, h1, l1;
    split2h(v.x, v.y, h0, l0); split2h(v.z, v.w, h1, l1);
    uint32_t* hp = reinterpret_cast<uint32_t*>(hi) + 2 * i;
    uint32_t* lp = reinterpret_cast<uint32_t*>(lo) + 2 * i;
    hp[0] = h0; hp[1] = h1; lp[0] = l0; lp[1] = l1;
}

__global__ void transpose_f16(const float* __restrict__ W,
                              __half* __restrict__ Wt,
                              int Kr, int Nc, int scale_lim, float scale) {
    __shared__ float tile[32][33];
    const int bx = blockIdx.x * 32, by = blockIdx.y * 32;
    const int tx = threadIdx.x, ty = threadIdx.y;
#pragma unroll
    for (int u = 0; u < 32; u += 8)
        tile[ty + u][tx] = W[(size_t)(by + ty + u) * Nc + bx + tx];
    __syncthreads();
#pragma unroll
    for (int u = 0; u < 32; u += 8) {
        const int n = bx + ty + u;
        float v = tile[tx][ty + u];
        if (n < scale_lim) v *= scale;
        Wt[(size_t)n * Kr + by + tx] = __float2half_rn(v);
    }
}

// ---------------------------------------------------------------------------
// 2-term split-fp16 GEMM: C = (Ah+Al) @ B^T, B = RN_fp16(W).
// CTA 128x128, 128 threads, 4 warps of 64x64 (R5-proven fragment shape).
// K-panel 32, 2-stage cp.async.
// ---------------------------------------------------------------------------
#define PANEL    32
#define RSTRIDE  80
#define TILE_B   (128 * RSTRIDE)        // 10240
#define SSTAGE   (3 * TILE_B)           // 30720 (Ah, Al, B)

__global__ __launch_bounds__(128, 2) void f16_gemm(const __half* __restrict__ Ah,
                                                   const __half* __restrict__ Al,
                                                   const __half* __restrict__ B,
                                                   float* __restrict__ C,
                                                   __half* __restrict__ Chi,
                                                   __half* __restrict__ Clo,
                                                   int M, int N, int K) {
    extern __shared__ char sm[];
    const uint32_t base = smem_u32(sm);

    const int t = threadIdx.x;
    const int wid = t >> 5, lane = t & 31;
    const int m0 = blockIdx.y * 128, n0 = blockIdx.x * 128;
    const int wm = (wid >> 1) * 64, wn = (wid & 1) * 64;
    const int NKI = K / PANEL;

    // cp.async: rg 0..31, sg 0..3; rows rg+{0,32,64,96} per tile, 3 tiles
    const int rg = t >> 2, sg = t & 3;
    const uint32_t s_off = (uint32_t)(rg * RSTRIDE + sg * 16);

#define LOAD_STAGE(i, s) do { \
        const size_t _k0 = (size_t)(i) * PANEL + sg * 8; \
        const uint32_t _st = base + (s) * SSTAGE + s_off; \
        _Pragma("unroll") \
        for (int _u = 0; _u < 4; ++_u) { \
            const int _r = rg + _u * 32; \
            const uint32_t _so = _st + _u * 32 * RSTRIDE; \
            CP16(_so,              Ah + (size_t)(m0 + _r) * K + _k0); \
            CP16(_so + TILE_B,     Al + (size_t)(m0 + _r) * K + _k0); \
            CP16(_so + 2 * TILE_B, B  + (size_t)(n0 + _r) * K + _k0); \
        } \
        CP_COMMIT(); \
    } while (0)

    uint32_t aoff[4], boff[4];
#pragma unroll
    for (int mt = 0; mt < 4; ++mt)
        aoff[mt] = (uint32_t)((wm + mt * 16 + (lane & 15)) * RSTRIDE + (lane >> 4) * 16);
#pragma unroll
    for (int p = 0; p < 4; ++p)
        boff[p] = (uint32_t)((wn + p * 16 + ((lane >> 4) << 3) + (lane & 7)) * RSTRIDE
                             + ((lane >> 3) & 1) * 16);

    float acc[4][8][4];
#pragma unroll
    for (int i = 0; i < 4; ++i)
#pragma unroll
        for (int j = 0; j < 8; ++j)
#pragma unroll
            for (int r = 0; r < 4; ++r) acc[i][j][r] = 0.0f;

    LOAD_STAGE(0, 0);

    for (int i = 0; i < NKI; ++i) {
        if (i + 1 < NKI) {
            LOAD_STAGE(i + 1, (i + 1) & 1);
            asm volatile("cp.async.wait_group 1;" ::: "memory");
        } else {
            asm volatile("cp.async.wait_group 0;" ::: "memory");
        }
        __syncthreads();

        const uint32_t sAh = base + (i & 1) * SSTAGE;
        const uint32_t sAl = sAh + TILE_B;
        const uint32_t sB  = sAh + 2 * TILE_B;

#pragma unroll
        for (int ks = 0; ks < 2; ++ks) {
            uint32_t ah[4][4], al[4][4];
#pragma unroll
            for (int mt = 0; mt < 4; ++mt) {
                LDSM4(ah[mt], sAh + aoff[mt] + ks * 32);
                LDSM4(al[mt], sAl + aoff[mt] + ks * 32);
            }
#pragma unroll
            for (int p = 0; p < 4; ++p) {
                uint32_t bf[4];
                LDSM4(bf, sB + boff[p] + ks * 32);
#pragma unroll
                for (int j = 0; j < 2; ++j) {
#pragma unroll
                    for (int mt = 0; mt < 4; ++mt) {
                        MMA_F16(acc[mt][2 * p + j], ah[mt], &bf[j * 2]);
                        MMA_F16(acc[mt][2 * p + j], al[mt], &bf[j * 2]);
                    }
                }
            }
        }
        __syncthreads();
    }

    const int r_lo = lane >> 2, c_lo = (lane & 3) * 2;
#pragma unroll
    for (int mt = 0; mt < 4; ++mt) {
        const int row = m0 + wm + mt * 16 + r_lo;
#pragma unroll
        for (int n8 = 0; n8 < 8; ++n8) {
            const int col = n0 + wn + n8 * 8 + c_lo;
            if (C) {
                *(float2*)(C + (size_t)row * N + col) =
                    make_float2(acc[mt][n8][0], acc[mt][n8][1]);
                *(float2*)(C + (size_t)(row + 8) * N + col) =
                    make_float2(acc[mt][n8][2], acc[mt][n8][3]);
            } else {
                uint32_t h, l;
                split2h(acc[mt][n8][0], acc[mt][n8][1], h, l);
                *(uint32_t*)(Chi + (size_t)row * N + col) = h;
                *(uint32_t*)(Clo + (size_t)row * N + col) = l;
                split2h(acc[mt][n8][2], acc[mt][n8][3], h, l);
                *(uint32_t*)(Chi + (size_t)(row + 8) * N + col) = h;
                *(uint32_t*)(Clo + (size_t)(row + 8) * N + col) = l;
            }
        }
    }
#undef LOAD_STAGE
}

// ---------------------------------------------------------------------------
// Tensor-core flash attention, fp16:
//   S = Qh K^T        (Q single fp16, K single fp16)
//   O += (Ph+Pl) V    (P split fp16, V single fp16)
// 256 thr / 8 warps; 128q x 128k tiles; double-buffered K/V (2 tiles/stage).
// ---------------------------------------------------------------------------
#define FAS    144
#define FTILE  (128 * FAS)
#define KVST   (2 * FTILE)              // Kh, Vh per stage

__global__ __launch_bounds__(256, 1) void flash_attn_tc(
    const __half* __restrict__ qkvh,
    __half* __restrict__ att_h,
    __half* __restrict__ att_l) {
    extern __shared__ char sm[];
    const uint32_t base  = smem_u32(sm);
    const uint32_t qbase = base + 2 * KVST;   // single Q tile

    const int qi = (int)gridDim.x - 1 - (int)blockIdx.x;
    const int bh = blockIdx.y;
    const int b  = bh >> 4, h = bh & 15;
    const int t  = threadIdx.x;
    const int wid = t >> 5, lane = t & 31;

    const int rowQ0 = b * T_SEQ + qi * 128;
    const int colQ = h * HEAD_DIM;
    const int colK = D_MODEL + h * HEAD_DIM;
    const int colV = 2 * D_MODEL + h * HEAD_DIM;

    const int rg = t >> 3, sg = t & 7;
    const uint32_t ls_off = (uint32_t)(rg * FAS + sg * 16);

#define LOADKV(kt, s) do { \
        const uint32_t _st = base + (s) * KVST + ls_off; \
        _Pragma("unroll") \
        for (int _u = 0; _u < 4; ++_u) { \
            const int _r = rg + _u * 32; \
            const size_t _row = (size_t)(b * T_SEQ + (kt) * 128 + _r) * QKV_N; \
            const uint32_t _so = _st + _u * 32 * FAS; \
            CP16(_so,         qkvh + _row + colK + sg * 8); \
            CP16(_so + FTILE, qkvh + _row + colV + sg * 8); \
        } \
        CP_COMMIT(); \
    } while (0)

    {
#pragma unroll
        for (int u = 0; u < 4; ++u) {
            const int r = rg + u * 32;
            const size_t row = (size_t)(rowQ0 + r) * QKV_N;
            CP16(qbase + ls_off + u * 32 * FAS, qkvh + row + colQ + sg * 8);
        }
        CP_COMMIT();
    }
    LOADKV(0, 0);

    asm volatile("cp.async.wait_group 1;" ::: "memory");
    __syncthreads();

    uint32_t qf[4][4];
    {
        const uint32_t aoff = (uint32_t)((wid * 16 + (lane & 15)) * FAS + (lane >> 4) * 16);
#pragma unroll
        for (int ks = 0; ks < 4; ++ks)
            LDSM4(qf[ks], qbase + aoff + ks * 32);
    }

    uint32_t koff[8];
#pragma unroll
    for (int p = 0; p < 8; ++p)
        koff[p] = (uint32_t)((p * 16 + ((lane >> 4) << 3) + (lane & 7)) * FAS
                             + ((lane >> 3) & 1) * 16);
    const int vg = lane >> 3;
    const uint32_t voff_r = (uint32_t)(((vg & 1) * 8 + (lane & 7)) * FAS + (vg >> 1) * 16);

    float O[8][4];
#pragma unroll
    for (int j = 0; j < 8; ++j)
#pragma unroll
        for (int r = 0; r < 4; ++r) O[j][r] = 0.0f;
    float m0 = -1e30f, m1 = -1e30f, l0 = 0.0f, l1 = 0.0f;

    const int r_lo = lane >> 2, c_lo = (lane & 3) * 2;
    const int row_loc0 = wid * 16 + r_lo;
    const int row_loc1 = row_loc0 + 8;

    for (int kt = 0; kt <= qi; ++kt) {
        if (kt + 1 <= qi) {
            LOADKV(kt + 1, (kt + 1) & 1);
            asm volatile("cp.async.wait_group 1;" ::: "memory");
        } else {
            asm volatile("cp.async.wait_group 0;" ::: "memory");
        }
        __syncthreads();

        const uint32_t sK = base + (kt & 1) * KVST;
        const uint32_t sV = sK + FTILE;

        // ---- S = Qh K^T (single-term)
        float s[16][4];
#pragma unroll
        for (int j = 0; j < 16; ++j)
#pragma unroll
            for (int r = 0; r < 4; ++r) s[j][r] = 0.0f;

#pragma unroll
        for (int ks = 0; ks < 4; ++ks) {
#pragma unroll
            for (int p = 0; p < 8; ++p) {
                uint32_t kb[4];
                LDSM4(kb, sK + koff[p] + ks * 32);
#pragma unroll
                for (int j = 0; j < 2; ++j)
                    MMA_F16(s[2 * p + j], qf[ks], &kb[j * 2]);
            }
        }

        if (kt == qi) {
#pragma unroll
            for (int n8 = 0; n8 < 16; ++n8) {
                const int c0 = n8 * 8 + c_lo;
                if (c0 > row_loc0)     s[n8][0] = -1e30f;
                if (c0 + 1 > row_loc0) s[n8][1] = -1e30f;
                if (c0 > row_loc1)     s[n8][2] = -1e30f;
                if (c0 + 1 > row_loc1) s[n8][3] = -1e30f;
            }
        }

        float mx0 = -1e30f, mx1 = -1e30f;
#pragma unroll
        for (int j = 0; j < 16; ++j) {
            mx0 = fmaxf(mx0, fmaxf(s[j][0], s[j][1]));
            mx1 = fmaxf(mx1, fmaxf(s[j][2], s[j][3]));
        }
#pragma unroll
        for (int off = 1; off <= 2; off <<= 1) {
            mx0 = fmaxf(mx0, __shfl_xor_sync(0xffffffffu, mx0, off, 32));
            mx1 = fmaxf(mx1, __shfl_xor_sync(0xffffffffu, mx1, off, 32));
        }
        const float mn0 = fmaxf(m0, mx0), mn1 = fmaxf(m1, mx1);
        const float cr0 = exp2f(m0 - mn0), cr1 = exp2f(m1 - mn1);
        float sum0 = 0.0f, sum1 = 0.0f;
#pragma unroll
        for (int j = 0; j < 16; ++j) {
            s[j][0] = exp2f(s[j][0] - mn0); sum0 += s[j][0];
            s[j][1] = exp2f(s[j][1] - mn0); sum0 += s[j][1];
            s[j][2] = exp2f(s[j][2] - mn1); sum1 += s[j][2];
            s[j][3] = exp2f(s[j][3] - mn1); sum1 += s[j][3];
        }
#pragma unroll
        for (int off = 1; off <= 2; off <<= 1) {
            sum0 += __shfl_xor_sync(0xffffffffu, sum0, off, 32);
            sum1 += __shfl_xor_sync(0xffffffffu, sum1, off, 32);
        }
        l0 = l0 * cr0 + sum0; l1 = l1 * cr1 + sum1;
        m0 = mn0; m1 = mn1;
#pragma unroll
        for (int j = 0; j < 8; ++j) {
            O[j][0] *= cr0; O[j][1] *= cr0; O[j][2] *= cr1; O[j][3] *= cr1;
        }

        // ---- O += (Ph+Pl) V, V single fp16
#pragma unroll
        for (int ks2 = 0; ks2 < 8; ++ks2) {
            uint32_t afh[4], afl[4];
            split2h(s[2 * ks2][0],     s[2 * ks2][1],     afh[0], afl[0]);
            split2h(s[2 * ks2][2],     s[2 * ks2][3],     afh[1], afl[1]);
            split2h(s[2 * ks2 + 1][0], s[2 * ks2 + 1][1], afh[2], afl[2]);
            split2h(s[2 * ks2 + 1][2], s[2 * ks2 + 1][3], afh[3], afl[3]);
            const uint32_t vrow = voff_r + ks2 * 16 * FAS;
#pragma unroll
            for (int j2 = 0; j2 < 4; ++j2) {
                uint32_t vb[4];
                LDSM4T(vb, sV + vrow + j2 * 32);
#pragma unroll
                for (int j = 0; j < 2; ++j) {
                    const int n8 = 2 * j2 + j;
                    MMA_F16(O[n8], afh, &vb[j * 2]);
                    MMA_F16(O[n8], afl, &vb[j * 2]);
                }
            }
        }
        __syncthreads();
    }

    // epilogue: normalize, split to fp16 hi/lo for the projection GEMM
    const float inv0 = 1.0f / l0, inv1 = 1.0f / l1;
    const int grow0 = rowQ0 + row_loc0;
    const int grow1 = rowQ0 + row_loc1;
#pragma unroll
    for (int n8 = 0; n8 < 8; ++n8) {
        const int col = h * HEAD_DIM + n8 * 8 + c_lo;
        uint32_t hh, ll;
        split2h(O[n8][0] * inv0, O[n8][1] * inv0, hh, ll);
        *(uint32_t*)(att_h + (size_t)grow0 * D_MODEL + col) = hh;
        *(uint32_t*)(att_l + (size_t)grow0 * D_MODEL + col) = ll;
        split2h(O[n8][2] * inv1, O[n8][3] * inv1, hh, ll);
        *(uint32_t*)(att_h + (size_t)grow1 * D_MODEL + col) = hh;
        *(uint32_t*)(att_l + (size_t)grow1 * D_MODEL + col) = ll;
    }
#undef LOADKV
}

// ---------------------------------------------------------------------------
extern "C" void kernel_launch(void* const* d_in, const int* in_sizes, int n_in,
                              void* d_out, int out_size) {
    const float* x     = (const float*)d_in[0];
    const float* W_qkv = (const float*)d_in[1];
    const float* W_out = (const float*)d_in[2];
    float*       out   = (float*)d_out;

    __half *qh, *ql2, *xh, *xl, *wq, *wo, *ath, *atl;
    cudaGetSymbolAddress((void**)&qh,  g_qkv_h);
    cudaGetSymbolAddress((void**)&ql2, g_qkv_l);
    cudaGetSymbolAddress((void**)&xh,  g_x_h);
    cudaGetSymbolAddress((void**)&xl,  g_x_l);
    cudaGetSymbolAddress((void**)&wq,  g_wqkv_h);
    cudaGetSymbolAddress((void**)&wo,  g_wout_h);
    cudaGetSymbolAddress((void**)&ath, g_att_h);
    cudaGetSymbolAddress((void**)&atl, g_att_l);

    const int smem_gemm = 2 * SSTAGE;                  // 61440
    const int smem_attn = 2 * KVST + FTILE;            // 92160
    cudaFuncSetAttribute(f16_gemm, cudaFuncAttributeMaxDynamicSharedMemorySize, smem_gemm);
    cudaFuncSetAttribute(flash_attn_tc, cudaFuncAttributeMaxDynamicSharedMemorySize, smem_attn);

    const float qscale = 0.125f * 1.4426950408889634f;  // fold log2(e) for exp2 softmax
    split_x_f16<<<(M_ROWS * D_MODEL / 4 + 255) / 256, 256>>>(
        (const float4*)x, xh, xl, M_ROWS * D_MODEL / 4);
    transpose_f16<<<dim3(QKV_N / 32, D_MODEL / 32), dim3(32, 8)>>>(
        W_qkv, wq, D_MODEL, QKV_N, D_MODEL, qscale);
    transpose_f16<<<dim3(D_MODEL / 32, D_MODEL / 32), dim3(32, 8)>>>(
        W_out, wo, D_MODEL, D_MODEL, 0, 1.0f);

    // 1) qkv = x @ W_qkv  (fp16 2-term; fp16 hi/lo output)
    f16_gemm<<<dim3(QKV_N / 128, M_ROWS / 128), 128, smem_gemm>>>(
        xh, xl, wq, nullptr, qh, ql2, M_ROWS, QKV_N, D_MODEL);

    // 2) causal flash attention (Q/K/V single fp16 S; split P)
    flash_attn_tc<<<dim3(T_SEQ / 128, B_SZ * N_HEADS), 256, smem_attn>>>(
        qh, ath, atl);

    // 3) out = att @ W_out  (fp16 2-term; fp32 output)
    f16_gemm<<<dim3(D_MODEL / 128, M_ROWS / 128), 128, smem_gemm>>>(
        ath, atl, wo, out, nullptr, nullptr, M_ROWS, D_MODEL, D_MODEL);
}

// round 13
// speedup vs baseline: 2.1695x; 1.4396x over previous
#include <cuda_runtime.h>
#include <cuda_fp16.h>
#include <math.h>
#include <cstdint>

#define D_MODEL   1024
#define T_SEQ     2048
#define B_SZ      4
#define N_HEADS   16
#define HEAD_DIM  64
#define M_ROWS    8192
#define QKV_N     3072

// Scratch (no cudaMalloc allowed)
__device__ __half  g_qkv_h[(size_t)M_ROWS * QKV_N];
__device__ __half  g_x_h[(size_t)M_ROWS * D_MODEL];
__device__ __half  g_att_h[(size_t)M_ROWS * D_MODEL];
__device__ __half  g_att_l[(size_t)M_ROWS * D_MODEL];
__device__ __half  g_wqkv_h[(size_t)QKV_N * D_MODEL];
__device__ __half  g_wout_h[(size_t)D_MODEL * D_MODEL];

__device__ __forceinline__ uint32_t smem_u32(const void* p) {
    uint32_t a;
    asm("{ .reg .u64 t; cvta.to.shared.u64 t, %1; cvt.u32.u64 %0, t; }" : "=r"(a) : "l"(p));
    return a;
}
__device__ __forceinline__ void split2h(float a, float b, uint32_t& h, uint32_t& l) {
    __half ha = __float2half_rn(a), hb = __float2half_rn(b);
    __half la = __float2half_rn(a - __half2float(ha));
    __half lb = __float2half_rn(b - __half2float(hb));
    __half2 hv = __halves2half2(ha, hb), lv = __halves2half2(la, lb);
    h = *reinterpret_cast<uint32_t*>(&hv);
    l = *reinterpret_cast<uint32_t*>(&lv);
}
__device__ __forceinline__ uint32_t pack_h2(float a, float b) {
    __half2 v = __floats2half2_rn(a, b);
    return *reinterpret_cast<uint32_t*>(&v);
}

#define LDSM4(r, addr) \
    asm volatile("ldmatrix.sync.aligned.m8n8.x4.shared.b16 {%0,%1,%2,%3}, [%4];" \
        : "=r"((r)[0]), "=r"((r)[1]), "=r"((r)[2]), "=r"((r)[3]) : "r"(addr))
#define LDSM4T(r, addr) \
    asm volatile("ldmatrix.sync.aligned.m8n8.x4.trans.shared.b16 {%0,%1,%2,%3}, [%4];" \
        : "=r"((r)[0]), "=r"((r)[1]), "=r"((r)[2]), "=r"((r)[3]) : "r"(addr))

#define MMA_F16(d, a, b) \
    asm volatile("mma.sync.aligned.m16n8k16.row.col.f32.f16.f16.f32 " \
        "{%0,%1,%2,%3}, {%4,%5,%6,%7}, {%8,%9}, {%0,%1,%2,%3};" \
        : "+f"((d)[0]), "+f"((d)[1]), "+f"((d)[2]), "+f"((d)[3]) \
        : "r"((a)[0]), "r"((a)[1]), "r"((a)[2]), "r"((a)[3]), "r"((b)[0]), "r"((b)[1]))

#define CP16(dst, src) \
    asm volatile("cp.async.cg.shared.global [%0], [%1], 16;" :: "r"(dst), "l"(src) : "memory")
#define CP_COMMIT() asm volatile("cp.async.commit_group;" ::: "memory")

// ---------------------------------------------------------------------------
// x (fp32) -> single fp16
__global__ void cvt_x_f16(const float4* __restrict__ x,
                          __half* __restrict__ hi, int n4) {
    const int i = blockIdx.x * 256 + threadIdx.x;
    if (i >= n4) return;
    float4 v = x[i];
    uint32_t* hp = reinterpret_cast<uint32_t*>(hi) + 2 * i;
    hp[0] = pack_h2(v.x, v.y);
    hp[1] = pack_h2(v.z, v.w);
}

__global__ void transpose_f16(const float* __restrict__ W,
                              __half* __restrict__ Wt,
                              int Kr, int Nc, int scale_lim, float scale) {
    __shared__ float tile[32][33];
    const int bx = blockIdx.x * 32, by = blockIdx.y * 32;
    const int tx = threadIdx.x, ty = threadIdx.y;
#pragma unroll
    for (int u = 0; u < 32; u += 8)
        tile[ty + u][tx] = W[(size_t)(by + ty + u) * Nc + bx + tx];
    __syncthreads();
#pragma unroll
    for (int u = 0; u < 32; u += 8) {
        const int n = bx + ty + u;
        float v = tile[tx][ty + u];
        if (n < scale_lim) v *= scale;
        Wt[(size_t)n * Kr + by + tx] = __float2half_rn(v);
    }
}

// ---------------------------------------------------------------------------
// fp16 GEMM, templated term count and output type.
//   TWO_TERM: C = (Ah+Al) @ B^T   else C = Ah @ B^T
//   F16OUT:   write half (RN of acc)  else write fp32
// CTA 128x128, 128 threads, 4 warps 64x64; K-panel 32, 2-stage cp.async.
// ---------------------------------------------------------------------------
#define PANEL    32
#define RSTRIDE  80
#define TILE_B   (128 * RSTRIDE)        // 10240

template<bool TWO_TERM, bool F16OUT>
__global__ __launch_bounds__(128, 2) void f16_gemm_t(const __half* __restrict__ Ah,
                                                     const __half* __restrict__ Al,
                                                     const __half* __restrict__ B,
                                                     float* __restrict__ C,
                                                     __half* __restrict__ Ch,
                                                     int M, int N, int K) {
    constexpr int NT = TWO_TERM ? 3 : 2;            // tiles per stage
    constexpr uint32_t SST = NT * TILE_B;
    extern __shared__ char sm[];
    const uint32_t base = smem_u32(sm);

    const int t = threadIdx.x;
    const int wid = t >> 5, lane = t & 31;
    const int m0 = blockIdx.y * 128, n0 = blockIdx.x * 128;
    const int wm = (wid >> 1) * 64, wn = (wid & 1) * 64;
    const int NKI = K / PANEL;

    const int rg = t >> 2, sg = t & 3;
    const uint32_t s_off = (uint32_t)(rg * RSTRIDE + sg * 16);

    auto load_stage = [&](int i, int s) {
        const size_t k0 = (size_t)i * PANEL + sg * 8;
        const uint32_t st = base + s * SST + s_off;
#pragma unroll
        for (int u = 0; u < 4; ++u) {
            const int r = rg + u * 32;
            const uint32_t so = st + u * 32 * RSTRIDE;
            CP16(so, Ah + (size_t)(m0 + r) * K + k0);
            if constexpr (TWO_TERM)
                CP16(so + TILE_B, Al + (size_t)(m0 + r) * K + k0);
            CP16(so + (NT - 1) * TILE_B, B + (size_t)(n0 + r) * K + k0);
        }
        CP_COMMIT();
    };

    uint32_t aoff[4], boff[4];
#pragma unroll
    for (int mt = 0; mt < 4; ++mt)
        aoff[mt] = (uint32_t)((wm + mt * 16 + (lane & 15)) * RSTRIDE + (lane >> 4) * 16);
#pragma unroll
    for (int p = 0; p < 4; ++p)
        boff[p] = (uint32_t)((wn + p * 16 + ((lane >> 4) << 3) + (lane & 7)) * RSTRIDE
                             + ((lane >> 3) & 1) * 16);

    float acc[4][8][4];
#pragma unroll
    for (int i = 0; i < 4; ++i)
#pragma unroll
        for (int j = 0; j < 8; ++j)
#pragma unroll
            for (int r = 0; r < 4; ++r) acc[i][j][r] = 0.0f;

    load_stage(0, 0);

    for (int i = 0; i < NKI; ++i) {
        if (i + 1 < NKI) {
            load_stage(i + 1, (i + 1) & 1);
            asm volatile("cp.async.wait_group 1;" ::: "memory");
        } else {
            asm volatile("cp.async.wait_group 0;" ::: "memory");
        }
        __syncthreads();

        const uint32_t sAh = base + (i & 1) * SST;
        const uint32_t sAl = sAh + TILE_B;                 // valid only if TWO_TERM
        const uint32_t sB  = sAh + (NT - 1) * TILE_B;

#pragma unroll
        for (int ks = 0; ks < 2; ++ks) {
            uint32_t ah[4][4], al[4][4];
#pragma unroll
            for (int mt = 0; mt < 4; ++mt) {
                LDSM4(ah[mt], sAh + aoff[mt] + ks * 32);
                if constexpr (TWO_TERM)
                    LDSM4(al[mt], sAl + aoff[mt] + ks * 32);
            }
#pragma unroll
            for (int p = 0; p < 4; ++p) {
                uint32_t bf[4];
                LDSM4(bf, sB + boff[p] + ks * 32);
#pragma unroll
                for (int j = 0; j < 2; ++j) {
#pragma unroll
                    for (int mt = 0; mt < 4; ++mt) {
                        MMA_F16(acc[mt][2 * p + j], ah[mt], &bf[j * 2]);
                        if constexpr (TWO_TERM)
                            MMA_F16(acc[mt][2 * p + j], al[mt], &bf[j * 2]);
                    }
                }
            }
        }
        __syncthreads();
    }

    const int r_lo = lane >> 2, c_lo = (lane & 3) * 2;
#pragma unroll
    for (int mt = 0; mt < 4; ++mt) {
        const int row = m0 + wm + mt * 16 + r_lo;
#pragma unroll
        for (int n8 = 0; n8 < 8; ++n8) {
            const int col = n0 + wn + n8 * 8 + c_lo;
            if constexpr (F16OUT) {
                *(uint32_t*)(Ch + (size_t)row * N + col) =
                    pack_h2(acc[mt][n8][0], acc[mt][n8][1]);
                *(uint32_t*)(Ch + (size_t)(row + 8) * N + col) =
                    pack_h2(acc[mt][n8][2], acc[mt][n8][3]);
            } else {
                *(float2*)(C + (size_t)row * N + col) =
                    make_float2(acc[mt][n8][0], acc[mt][n8][1]);
                *(float2*)(C + (size_t)(row + 8) * N + col) =
                    make_float2(acc[mt][n8][2], acc[mt][n8][3]);
            }
        }
    }
}

// ---------------------------------------------------------------------------
// Tensor-core flash attention, all-single-fp16 MMA inputs:
//   S = Qh K^T ; O += Ph V   (P = RN_fp16(softmax), V = hi)
// Epilogue emits att as fp16 hi/lo (2-term input for the projection GEMM).
// 256 thr / 8 warps; 128q x 128k tiles; double-buffered K/V.
// ---------------------------------------------------------------------------
#define FAS    144
#define FTILE  (128 * FAS)
#define KVST   (2 * FTILE)              // Kh, Vh per stage

__global__ __launch_bounds__(256, 1) void flash_attn_tc(
    const __half* __restrict__ qkvh,
    __half* __restrict__ att_h,
    __half* __restrict__ att_l) {
    extern __shared__ char sm[];
    const uint32_t base  = smem_u32(sm);
    const uint32_t qbase = base + 2 * KVST;   // single Q tile

    const int qi = (int)gridDim.x - 1 - (int)blockIdx.x;
    const int bh = blockIdx.y;
    const int b  = bh >> 4, h = bh & 15;
    const int t  = threadIdx.x;
    const int wid = t >> 5, lane = t & 31;

    const int rowQ0 = b * T_SEQ + qi * 128;
    const int colQ = h * HEAD_DIM;
    const int colK = D_MODEL + h * HEAD_DIM;
    const int colV = 2 * D_MODEL + h * HEAD_DIM;

    const int rg = t >> 3, sg = t & 7;
    const uint32_t ls_off = (uint32_t)(rg * FAS + sg * 16);

#define LOADKV(kt, s) do { \
        const uint32_t _st = base + (s) * KVST + ls_off; \
        _Pragma("unroll") \
        for (int _u = 0; _u < 4; ++_u) { \
            const int _r = rg + _u * 32; \
            const size_t _row = (size_t)(b * T_SEQ + (kt) * 128 + _r) * QKV_N; \
            const uint32_t _so = _st + _u * 32 * FAS; \
            CP16(_so,         qkvh + _row + colK + sg * 8); \
            CP16(_so + FTILE, qkvh + _row + colV + sg * 8); \
        } \
        CP_COMMIT(); \
    } while (0)

    {
#pragma unroll
        for (int u = 0; u < 4; ++u) {
            const int r = rg + u * 32;
            const size_t row = (size_t)(rowQ0 + r) * QKV_N;
            CP16(qbase + ls_off + u * 32 * FAS, qkvh + row + colQ + sg * 8);
        }
        CP_COMMIT();
    }
    LOADKV(0, 0);

    asm volatile("cp.async.wait_group 1;" ::: "memory");
    __syncthreads();

    uint32_t qf[4][4];
    {
        const uint32_t aoff = (uint32_t)((wid * 16 + (lane & 15)) * FAS + (lane >> 4) * 16);
#pragma unroll
        for (int ks = 0; ks < 4; ++ks)
            LDSM4(qf[ks], qbase + aoff + ks * 32);
    }

    uint32_t koff[8];
#pragma unroll
    for (int p = 0; p < 8; ++p)
        koff[p] = (uint32_t)((p * 16 + ((lane >> 4) << 3) + (lane & 7)) * FAS
                             + ((lane >> 3) & 1) * 16);
    const int vg = lane >> 3;
    const uint32_t voff_r = (uint32_t)(((vg & 1) * 8 + (lane & 7)) * FAS + (vg >> 1) * 16);

    float O[8][4];
#pragma unroll
    for (int j = 0; j < 8; ++j)
#pragma unroll
        for (int r = 0; r < 4; ++r) O[j][r] = 0.0f;
    float m0 = -1e30f, m1 = -1e30f, l0 = 0.0f, l1 = 0.0f;

    const int r_lo = lane >> 2, c_lo = (lane & 3) * 2;
    const int row_loc0 = wid * 16 + r_lo;
    const int row_loc1 = row_loc0 + 8;

    for (int kt = 0; kt <= qi; ++kt) {
        if (kt + 1 <= qi) {
            LOADKV(kt + 1, (kt + 1) & 1);
            asm volatile("cp.async.wait_group 1;" ::: "memory");
        } else {
            asm volatile("cp.async.wait_group 0;" ::: "memory");
        }
        __syncthreads();

        const uint32_t sK = base + (kt & 1) * KVST;
        const uint32_t sV = sK + FTILE;

        // ---- S = Qh K^T
        float s[16][4];
#pragma unroll
        for (int j = 0; j < 16; ++j)
#pragma unroll
            for (int r = 0; r < 4; ++r) s[j][r] = 0.0f;

#pragma unroll
        for (int ks = 0; ks < 4; ++ks) {
#pragma unroll
            for (int p = 0; p < 8; ++p) {
                uint32_t kb[4];
                LDSM4(kb, sK + koff[p] + ks * 32);
#pragma unroll
                for (int j = 0; j < 2; ++j)
                    MMA_F16(s[2 * p + j], qf[ks], &kb[j * 2]);
            }
        }

        if (kt == qi) {
#pragma unroll
            for (int n8 = 0; n8 < 16; ++n8) {
                const int c0 = n8 * 8 + c_lo;
                if (c0 > row_loc0)     s[n8][0] = -1e30f;
                if (c0 + 1 > row_loc0) s[n8][1] = -1e30f;
                if (c0 > row_loc1)     s[n8][2] = -1e30f;
                if (c0 + 1 > row_loc1) s[n8][3] = -1e30f;
            }
        }

        float mx0 = -1e30f, mx1 = -1e30f;
#pragma unroll
        for (int j = 0; j < 16; ++j) {
            mx0 = fmaxf(mx0, fmaxf(s[j][0], s[j][1]));
            mx1 = fmaxf(mx1, fmaxf(s[j][2], s[j][3]));
        }
#pragma unroll
        for (int off = 1; off <= 2; off <<= 1) {
            mx0 = fmaxf(mx0, __shfl_xor_sync(0xffffffffu, mx0, off, 32));
            mx1 = fmaxf(mx1, __shfl_xor_sync(0xffffffffu, mx1, off, 32));
        }
        const float mn0 = fmaxf(m0, mx0), mn1 = fmaxf(m1, mx1);
        const float cr0 = exp2f(m0 - mn0), cr1 = exp2f(m1 - mn1);
        float sum0 = 0.0f, sum1 = 0.0f;
#pragma unroll
        for (int j = 0; j < 16; ++j) {
            s[j][0] = exp2f(s[j][0] - mn0); sum0 += s[j][0];
            s[j][1] = exp2f(s[j][1] - mn0); sum0 += s[j][1];
            s[j][2] = exp2f(s[j][2] - mn1); sum1 += s[j][2];
            s[j][3] = exp2f(s[j][3] - mn1); sum1 += s[j][3];
        }
#pragma unroll
        for (int off = 1; off <= 2; off <<= 1) {
            sum0 += __shfl_xor_sync(0xffffffffu, sum0, off, 32);
            sum1 += __shfl_xor_sync(0xffffffffu, sum1, off, 32);
        }
        l0 = l0 * cr0 + sum0; l1 = l1 * cr1 + sum1;
        m0 = mn0; m1 = mn1;
#pragma unroll
        for (int j = 0; j < 8; ++j) {
            O[j][0] *= cr0; O[j][1] *= cr0; O[j][2] *= cr1; O[j][3] *= cr1;
        }

        // ---- O += Ph V (P single fp16)
#pragma unroll
        for (int ks2 = 0; ks2 < 8; ++ks2) {
            uint32_t af[4];
            af[0] = pack_h2(s[2 * ks2][0],     s[2 * ks2][1]);
            af[1] = pack_h2(s[2 * ks2][2],     s[2 * ks2][3]);
            af[2] = pack_h2(s[2 * ks2 + 1][0], s[2 * ks2 + 1][1]);
            af[3] = pack_h2(s[2 * ks2 + 1][2], s[2 * ks2 + 1][3]);
            const uint32_t vrow = voff_r + ks2 * 16 * FAS;
#pragma unroll
            for (int j2 = 0; j2 < 4; ++j2) {
                uint32_t vb[4];
                LDSM4T(vb, sV + vrow + j2 * 32);
#pragma unroll
                for (int j = 0; j < 2; ++j)
                    MMA_F16(O[2 * j2 + j], af, &vb[j * 2]);
            }
        }
        __syncthreads();
    }

    // epilogue: normalize, split to fp16 hi/lo for the projection GEMM
    const float inv0 = 1.0f / l0, inv1 = 1.0f / l1;
    const int grow0 = rowQ0 + row_loc0;
    const int grow1 = rowQ0 + row_loc1;
#pragma unroll
    for (int n8 = 0; n8 < 8; ++n8) {
        const int col = h * HEAD_DIM + n8 * 8 + c_lo;
        uint32_t hh, ll;
        split2h(O[n8][0] * inv0, O[n8][1] * inv0, hh, ll);
        *(uint32_t*)(att_h + (size_t)grow0 * D_MODEL + col) = hh;
        *(uint32_t*)(att_l + (size_t)grow0 * D_MODEL + col) = ll;
        split2h(O[n8][2] * inv1, O[n8][3] * inv1, hh, ll);
        *(uint32_t*)(att_h + (size_t)grow1 * D_MODEL + col) = hh;
        *(uint32_t*)(att_l + (size_t)grow1 * D_MODEL + col) = ll;
    }
#undef LOADKV
}

// ---------------------------------------------------------------------------
extern "C" void kernel_launch(void* const* d_in, const int* in_sizes, int n_in,
                              void* d_out, int out_size) {
    const float* x     = (const float*)d_in[0];
    const float* W_qkv = (const float*)d_in[1];
    const float* W_out = (const float*)d_in[2];
    float*       out   = (float*)d_out;

    __half *qh, *xh, *wq, *wo, *ath, *atl;
    cudaGetSymbolAddress((void**)&qh,  g_qkv_h);
    cudaGetSymbolAddress((void**)&xh,  g_x_h);
    cudaGetSymbolAddress((void**)&wq,  g_wqkv_h);
    cudaGetSymbolAddress((void**)&wo,  g_wout_h);
    cudaGetSymbolAddress((void**)&ath, g_att_h);
    cudaGetSymbolAddress((void**)&atl, g_att_l);

    const int smem_g1  = 2 * 2 * TILE_B;               // 40960 (1-term)
    const int smem_g3  = 2 * 3 * TILE_B;               // 61440 (2-term)
    const int smem_attn = 2 * KVST + FTILE;            // 92160
    cudaFuncSetAttribute((const void*)f16_gemm_t<false, true>,
                         cudaFuncAttributeMaxDynamicSharedMemorySize, smem_g1);
    cudaFuncSetAttribute((const void*)f16_gemm_t<true, false>,
                         cudaFuncAttributeMaxDynamicSharedMemorySize, smem_g3);
    cudaFuncSetAttribute(flash_attn_tc, cudaFuncAttributeMaxDynamicSharedMemorySize, smem_attn);

    const float qscale = 0.125f * 1.4426950408889634f;  // fold log2(e) for exp2 softmax
    cvt_x_f16<<<(M_ROWS * D_MODEL / 4 + 255) / 256, 256>>>(
        (const float4*)x, xh, M_ROWS * D_MODEL / 4);
    transpose_f16<<<dim3(QKV_N / 32, D_MODEL / 32), dim3(32, 8)>>>(
        W_qkv, wq, D_MODEL, QKV_N, D_MODEL, qscale);
    transpose_f16<<<dim3(D_MODEL / 32, D_MODEL / 32), dim3(32, 8)>>>(
        W_out, wo, D_MODEL, D_MODEL, 0, 1.0f);

    // 1) qkv = x_h @ W_qkv  (single-term fp16; fp16 output)
    f16_gemm_t<false, true><<<dim3(QKV_N / 128, M_ROWS / 128), 128, smem_g1>>>(
        xh, nullptr, wq, nullptr, qh, M_ROWS, QKV_N, D_MODEL);

    // 2) causal flash attention (single-fp16 Q/K/V/P; att hi/lo out)
    flash_attn_tc<<<dim3(T_SEQ / 128, B_SZ * N_HEADS), 256, smem_attn>>>(
        qh, ath, atl);

    // 3) out = (att_h + att_l) @ W_out  (2-term; fp32 output)
    f16_gemm_t<true, false><<<dim3(D_MODEL / 128, M_ROWS / 128), 128, smem_g3>>>(
        ath, atl, wo, out, nullptr, M_ROWS, D_MODEL, D_MODEL);
}

// round 14
// speedup vs baseline: 2.4566x; 1.1323x over previous
#include <cuda_runtime.h>
#include <cuda_fp16.h>
#include <math.h>
#include <cstdint>

#define D_MODEL   1024
#define T_SEQ     2048
#define B_SZ      4
#define N_HEADS   16
#define HEAD_DIM  64
#define M_ROWS    8192
#define QKV_N     3072

// Scratch (no cudaMalloc allowed)
__device__ __half  g_qkv_h[(size_t)M_ROWS * QKV_N];
__device__ __half  g_x_h[(size_t)M_ROWS * D_MODEL];
__device__ __half  g_att_h[(size_t)M_ROWS * D_MODEL];
__device__ __half  g_wqkv_h[(size_t)QKV_N * D_MODEL];
__device__ __half  g_wout_h[(size_t)D_MODEL * D_MODEL];

__device__ __forceinline__ uint32_t smem_u32(const void* p) {
    uint32_t a;
    asm("{ .reg .u64 t; cvta.to.shared.u64 t, %1; cvt.u32.u64 %0, t; }" : "=r"(a) : "l"(p));
    return a;
}
__device__ __forceinline__ uint32_t pack_h2(float a, float b) {
    __half2 v = __floats2half2_rn(a, b);
    return *reinterpret_cast<uint32_t*>(&v);
}

#define LDSM4(r, addr) \
    asm volatile("ldmatrix.sync.aligned.m8n8.x4.shared.b16 {%0,%1,%2,%3}, [%4];" \
        : "=r"((r)[0]), "=r"((r)[1]), "=r"((r)[2]), "=r"((r)[3]) : "r"(addr))
#define LDSM4T(r, addr) \
    asm volatile("ldmatrix.sync.aligned.m8n8.x4.trans.shared.b16 {%0,%1,%2,%3}, [%4];" \
        : "=r"((r)[0]), "=r"((r)[1]), "=r"((r)[2]), "=r"((r)[3]) : "r"(addr))

#define MMA_F16(d, a, b) \
    asm volatile("mma.sync.aligned.m16n8k16.row.col.f32.f16.f16.f32 " \
        "{%0,%1,%2,%3}, {%4,%5,%6,%7}, {%8,%9}, {%0,%1,%2,%3};" \
        : "+f"((d)[0]), "+f"((d)[1]), "+f"((d)[2]), "+f"((d)[3]) \
        : "r"((a)[0]), "r"((a)[1]), "r"((a)[2]), "r"((a)[3]), "r"((b)[0]), "r"((b)[1]))

#define CP16(dst, src) \
    asm volatile("cp.async.cg.shared.global [%0], [%1], 16;" :: "r"(dst), "l"(src) : "memory")
#define CP_COMMIT() asm volatile("cp.async.commit_group;" ::: "memory")

// ---------------------------------------------------------------------------
__global__ void cvt_x_f16(const float4* __restrict__ x,
                          __half* __restrict__ hi, int n4) {
    const int i = blockIdx.x * 256 + threadIdx.x;
    if (i >= n4) return;
    float4 v = x[i];
    uint32_t* hp = reinterpret_cast<uint32_t*>(hi) + 2 * i;
    hp[0] = pack_h2(v.x, v.y);
    hp[1] = pack_h2(v.z, v.w);
}

__global__ void transpose_f16(const float* __restrict__ W,
                              __half* __restrict__ Wt,
                              int Kr, int Nc, int scale_lim, float scale) {
    __shared__ float tile[32][33];
    const int bx = blockIdx.x * 32, by = blockIdx.y * 32;
    const int tx = threadIdx.x, ty = threadIdx.y;
#pragma unroll
    for (int u = 0; u < 32; u += 8)
        tile[ty + u][tx] = W[(size_t)(by + ty + u) * Nc + bx + tx];
    __syncthreads();
#pragma unroll
    for (int u = 0; u < 32; u += 8) {
        const int n = bx + ty + u;
        float v = tile[tx][ty + u];
        if (n < scale_lim) v *= scale;
        Wt[(size_t)n * Kr + by + tx] = __float2half_rn(v);
    }
}

// ---------------------------------------------------------------------------
// Single-term fp16 GEMM: C = A @ B^T  (A, B fp16; fp32 acc).
//   F16OUT: write half (RN of acc) else fp32.
// CTA 128x128, 128 threads, 4 warps 64x64; K-panel 32, 2-stage cp.async.
// ---------------------------------------------------------------------------
#define PANEL    32
#define RSTRIDE  80
#define TILE_B   (128 * RSTRIDE)        // 10240
#define SST      (2 * TILE_B)           // A, B per stage

template<bool F16OUT>
__global__ __launch_bounds__(128, 2) void f16_gemm_t(const __half* __restrict__ A,
                                                     const __half* __restrict__ B,
                                                     float* __restrict__ C,
                                                     __half* __restrict__ Ch,
                                                     int M, int N, int K) {
    extern __shared__ char sm[];
    const uint32_t base = smem_u32(sm);

    const int t = threadIdx.x;
    const int wid = t >> 5, lane = t & 31;
    const int m0 = blockIdx.y * 128, n0 = blockIdx.x * 128;
    const int wm = (wid >> 1) * 64, wn = (wid & 1) * 64;
    const int NKI = K / PANEL;

    const int rg = t >> 2, sg = t & 3;
    const uint32_t s_off = (uint32_t)(rg * RSTRIDE + sg * 16);

    auto load_stage = [&](int i, int s) {
        const size_t k0 = (size_t)i * PANEL + sg * 8;
        const uint32_t st = base + s * SST + s_off;
#pragma unroll
        for (int u = 0; u < 4; ++u) {
            const int r = rg + u * 32;
            const uint32_t so = st + u * 32 * RSTRIDE;
            CP16(so,          A + (size_t)(m0 + r) * K + k0);
            CP16(so + TILE_B, B + (size_t)(n0 + r) * K + k0);
        }
        CP_COMMIT();
    };

    uint32_t aoff[4], boff[4];
#pragma unroll
    for (int mt = 0; mt < 4; ++mt)
        aoff[mt] = (uint32_t)((wm + mt * 16 + (lane & 15)) * RSTRIDE + (lane >> 4) * 16);
#pragma unroll
    for (int p = 0; p < 4; ++p)
        boff[p] = (uint32_t)((wn + p * 16 + ((lane >> 4) << 3) + (lane & 7)) * RSTRIDE
                             + ((lane >> 3) & 1) * 16);

    float acc[4][8][4];
#pragma unroll
    for (int i = 0; i < 4; ++i)
#pragma unroll
        for (int j = 0; j < 8; ++j)
#pragma unroll
            for (int r = 0; r < 4; ++r) acc[i][j][r] = 0.0f;

    load_stage(0, 0);

    for (int i = 0; i < NKI; ++i) {
        if (i + 1 < NKI) {
            load_stage(i + 1, (i + 1) & 1);
            asm volatile("cp.async.wait_group 1;" ::: "memory");
        } else {
            asm volatile("cp.async.wait_group 0;" ::: "memory");
        }
        __syncthreads();

        const uint32_t sA = base + (i & 1) * SST;
        const uint32_t sB = sA + TILE_B;

#pragma unroll
        for (int ks = 0; ks < 2; ++ks) {
            uint32_t af[4][4];
#pragma unroll
            for (int mt = 0; mt < 4; ++mt)
                LDSM4(af[mt], sA + aoff[mt] + ks * 32);
#pragma unroll
            for (int p = 0; p < 4; ++p) {
                uint32_t bf[4];
                LDSM4(bf, sB + boff[p] + ks * 32);
#pragma unroll
                for (int j = 0; j < 2; ++j)
#pragma unroll
                    for (int mt = 0; mt < 4; ++mt)
                        MMA_F16(acc[mt][2 * p + j], af[mt], &bf[j * 2]);
            }
        }
        __syncthreads();
    }

    const int r_lo = lane >> 2, c_lo = (lane & 3) * 2;
#pragma unroll
    for (int mt = 0; mt < 4; ++mt) {
        const int row = m0 + wm + mt * 16 + r_lo;
#pragma unroll
        for (int n8 = 0; n8 < 8; ++n8) {
            const int col = n0 + wn + n8 * 8 + c_lo;
            if constexpr (F16OUT) {
                *(uint32_t*)(Ch + (size_t)row * N + col) =
                    pack_h2(acc[mt][n8][0], acc[mt][n8][1]);
                *(uint32_t*)(Ch + (size_t)(row + 8) * N + col) =
                    pack_h2(acc[mt][n8][2], acc[mt][n8][3]);
            } else {
                *(float2*)(C + (size_t)row * N + col) =
                    make_float2(acc[mt][n8][0], acc[mt][n8][1]);
                *(float2*)(C + (size_t)(row + 8) * N + col) =
                    make_float2(acc[mt][n8][2], acc[mt][n8][3]);
            }
        }
    }
}

// ---------------------------------------------------------------------------
// Tensor-core flash attention, all-single-fp16 MMA inputs:
//   S = Qh K^T ; O += Ph V.  Epilogue emits att as single fp16.
// 256 thr / 8 warps; 128q x 128k tiles; double-buffered K/V.
// ---------------------------------------------------------------------------
#define FAS    144
#define FTILE  (128 * FAS)
#define KVST   (2 * FTILE)              // Kh, Vh per stage

__global__ __launch_bounds__(256, 1) void flash_attn_tc(
    const __half* __restrict__ qkvh,
    __half* __restrict__ att_h) {
    extern __shared__ char sm[];
    const uint32_t base  = smem_u32(sm);
    const uint32_t qbase = base + 2 * KVST;   // single Q tile

    const int qi = (int)gridDim.x - 1 - (int)blockIdx.x;
    const int bh = blockIdx.y;
    const int b  = bh >> 4, h = bh & 15;
    const int t  = threadIdx.x;
    const int wid = t >> 5, lane = t & 31;

    const int rowQ0 = b * T_SEQ + qi * 128;
    const int colQ = h * HEAD_DIM;
    const int colK = D_MODEL + h * HEAD_DIM;
    const int colV = 2 * D_MODEL + h * HEAD_DIM;

    const int rg = t >> 3, sg = t & 7;
    const uint32_t ls_off = (uint32_t)(rg * FAS + sg * 16);

#define LOADKV(kt, s) do { \
        const uint32_t _st = base + (s) * KVST + ls_off; \
        _Pragma("unroll") \
        for (int _u = 0; _u < 4; ++_u) { \
            const int _r = rg + _u * 32; \
            const size_t _row = (size_t)(b * T_SEQ + (kt) * 128 + _r) * QKV_N; \
            const uint32_t _so = _st + _u * 32 * FAS; \
            CP16(_so,         qkvh + _row + colK + sg * 8); \
            CP16(_so + FTILE, qkvh + _row + colV + sg * 8); \
        } \
        CP_COMMIT(); \
    } while (0)

    {
#pragma unroll
        for (int u = 0; u < 4; ++u) {
            const int r = rg + u * 32;
            const size_t row = (size_t)(rowQ0 + r) * QKV_N;
            CP16(qbase + ls_off + u * 32 * FAS, qkvh + row + colQ + sg * 8);
        }
        CP_COMMIT();
    }
    LOADKV(0, 0);

    asm volatile("cp.async.wait_group 1;" ::: "memory");
    __syncthreads();

    uint32_t qf[4][4];
    {
        const uint32_t aoff = (uint32_t)((wid * 16 + (lane & 15)) * FAS + (lane >> 4) * 16);
#pragma unroll
        for (int ks = 0; ks < 4; ++ks)
            LDSM4(qf[ks], qbase + aoff + ks * 32);
    }

    uint32_t koff[8];
#pragma unroll
    for (int p = 0; p < 8; ++p)
        koff[p] = (uint32_t)((p * 16 + ((lane >> 4) << 3) + (lane & 7)) * FAS
                             + ((lane >> 3) & 1) * 16);
    const int vg = lane >> 3;
    const uint32_t voff_r = (uint32_t)(((vg & 1) * 8 + (lane & 7)) * FAS + (vg >> 1) * 16);

    float O[8][4];
#pragma unroll
    for (int j = 0; j < 8; ++j)
#pragma unroll
        for (int r = 0; r < 4; ++r) O[j][r] = 0.0f;
    float m0 = -1e30f, m1 = -1e30f, l0 = 0.0f, l1 = 0.0f;

    const int r_lo = lane >> 2, c_lo = (lane & 3) * 2;
    const int row_loc0 = wid * 16 + r_lo;
    const int row_loc1 = row_loc0 + 8;

    for (int kt = 0; kt <= qi; ++kt) {
        if (kt + 1 <= qi) {
            LOADKV(kt + 1, (kt + 1) & 1);
            asm volatile("cp.async.wait_group 1;" ::: "memory");
        } else {
            asm volatile("cp.async.wait_group 0;" ::: "memory");
        }
        __syncthreads();

        const uint32_t sK = base + (kt & 1) * KVST;
        const uint32_t sV = sK + FTILE;

        // ---- S = Qh K^T
        float s[16][4];
#pragma unroll
        for (int j = 0; j < 16; ++j)
#pragma unroll
            for (int r = 0; r < 4; ++r) s[j][r] = 0.0f;

#pragma unroll
        for (int ks = 0; ks < 4; ++ks) {
#pragma unroll
            for (int p = 0; p < 8; ++p) {
                uint32_t kb[4];
                LDSM4(kb, sK + koff[p] + ks * 32);
#pragma unroll
                for (int j = 0; j < 2; ++j)
                    MMA_F16(s[2 * p + j], qf[ks], &kb[j * 2]);
            }
        }

        if (kt == qi) {
#pragma unroll
            for (int n8 = 0; n8 < 16; ++n8) {
                const int c0 = n8 * 8 + c_lo;
                if (c0 > row_loc0)     s[n8][0] = -1e30f;
                if (c0 + 1 > row_loc0) s[n8][1] = -1e30f;
                if (c0 > row_loc1)     s[n8][2] = -1e30f;
                if (c0 + 1 > row_loc1) s[n8][3] = -1e30f;
            }
        }

        float mx0 = -1e30f, mx1 = -1e30f;
#pragma unroll
        for (int j = 0; j < 16; ++j) {
            mx0 = fmaxf(mx0, fmaxf(s[j][0], s[j][1]));
            mx1 = fmaxf(mx1, fmaxf(s[j][2], s[j][3]));
        }
#pragma unroll
        for (int off = 1; off <= 2; off <<= 1) {
            mx0 = fmaxf(mx0, __shfl_xor_sync(0xffffffffu, mx0, off, 32));
            mx1 = fmaxf(mx1, __shfl_xor_sync(0xffffffffu, mx1, off, 32));
        }
        const float mn0 = fmaxf(m0, mx0), mn1 = fmaxf(m1, mx1);
        const float cr0 = exp2f(m0 - mn0), cr1 = exp2f(m1 - mn1);
        float sum0 = 0.0f, sum1 = 0.0f;
#pragma unroll
        for (int j = 0; j < 16; ++j) {
            s[j][0] = exp2f(s[j][0] - mn0); sum0 += s[j][0];
            s[j][1] = exp2f(s[j][1] - mn0); sum0 += s[j][1];
            s[j][2] = exp2f(s[j][2] - mn1); sum1 += s[j][2];
            s[j][3] = exp2f(s[j][3] - mn1); sum1 += s[j][3];
        }
#pragma unroll
        for (int off = 1; off <= 2; off <<= 1) {
            sum0 += __shfl_xor_sync(0xffffffffu, sum0, off, 32);
            sum1 += __shfl_xor_sync(0xffffffffu, sum1, off, 32);
        }
        l0 = l0 * cr0 + sum0; l1 = l1 * cr1 + sum1;
        m0 = mn0; m1 = mn1;
#pragma unroll
        for (int j = 0; j < 8; ++j) {
            O[j][0] *= cr0; O[j][1] *= cr0; O[j][2] *= cr1; O[j][3] *= cr1;
        }

        // ---- O += Ph V
#pragma unroll
        for (int ks2 = 0; ks2 < 8; ++ks2) {
            uint32_t af[4];
            af[0] = pack_h2(s[2 * ks2][0],     s[2 * ks2][1]);
            af[1] = pack_h2(s[2 * ks2][2],     s[2 * ks2][3]);
            af[2] = pack_h2(s[2 * ks2 + 1][0], s[2 * ks2 + 1][1]);
            af[3] = pack_h2(s[2 * ks2 + 1][2], s[2 * ks2 + 1][3]);
            const uint32_t vrow = voff_r + ks2 * 16 * FAS;
#pragma unroll
            for (int j2 = 0; j2 < 4; ++j2) {
                uint32_t vb[4];
                LDSM4T(vb, sV + vrow + j2 * 32);
#pragma unroll
                for (int j = 0; j < 2; ++j)
                    MMA_F16(O[2 * j2 + j], af, &vb[j * 2]);
            }
        }
        __syncthreads();
    }

    // epilogue: normalize, single fp16 out
    const float inv0 = 1.0f / l0, inv1 = 1.0f / l1;
    const int grow0 = rowQ0 + row_loc0;
    const int grow1 = rowQ0 + row_loc1;
#pragma unroll
    for (int n8 = 0; n8 < 8; ++n8) {
        const int col = h * HEAD_DIM + n8 * 8 + c_lo;
        *(uint32_t*)(att_h + (size_t)grow0 * D_MODEL + col) =
            pack_h2(O[n8][0] * inv0, O[n8][1] * inv0);
        *(uint32_t*)(att_h + (size_t)grow1 * D_MODEL + col) =
            pack_h2(O[n8][2] * inv1, O[n8][3] * inv1);
    }
#undef LOADKV
}

// ---------------------------------------------------------------------------
extern "C" void kernel_launch(void* const* d_in, const int* in_sizes, int n_in,
                              void* d_out, int out_size) {
    const float* x     = (const float*)d_in[0];
    const float* W_qkv = (const float*)d_in[1];
    const float* W_out = (const float*)d_in[2];
    float*       out   = (float*)d_out;

    __half *qh, *xh, *wq, *wo, *ath;
    cudaGetSymbolAddress((void**)&qh,  g_qkv_h);
    cudaGetSymbolAddress((void**)&xh,  g_x_h);
    cudaGetSymbolAddress((void**)&wq,  g_wqkv_h);
    cudaGetSymbolAddress((void**)&wo,  g_wout_h);
    cudaGetSymbolAddress((void**)&ath, g_att_h);

    const int smem_gemm = 2 * SST;                     // 40960
    const int smem_attn = 2 * KVST + FTILE;            // 92160
    cudaFuncSetAttribute((const void*)f16_gemm_t<true>,
                         cudaFuncAttributeMaxDynamicSharedMemorySize, smem_gemm);
    cudaFuncSetAttribute((const void*)f16_gemm_t<false>,
                         cudaFuncAttributeMaxDynamicSharedMemorySize, smem_gemm);
    cudaFuncSetAttribute(flash_attn_tc, cudaFuncAttributeMaxDynamicSharedMemorySize, smem_attn);

    const float qscale = 0.125f * 1.4426950408889634f;  // fold log2(e) for exp2 softmax
    cvt_x_f16<<<(M_ROWS * D_MODEL / 4 + 255) / 256, 256>>>(
        (const float4*)x, xh, M_ROWS * D_MODEL / 4);
    transpose_f16<<<dim3(QKV_N / 32, D_MODEL / 32), dim3(32, 8)>>>(
        W_qkv, wq, D_MODEL, QKV_N, D_MODEL, qscale);
    transpose_f16<<<dim3(D_MODEL / 32, D_MODEL / 32), dim3(32, 8)>>>(
        W_out, wo, D_MODEL, D_MODEL, 0, 1.0f);

    // 1) qkv = x_h @ W_qkv  (fp16 out)
    f16_gemm_t<true><<<dim3(QKV_N / 128, M_ROWS / 128), 128, smem_gemm>>>(
        xh, wq, nullptr, qh, M_ROWS, QKV_N, D_MODEL);

    // 2) causal flash attention (fp16 out)
    flash_attn_tc<<<dim3(T_SEQ / 128, B_SZ * N_HEADS), 256, smem_attn>>>(qh, ath);

    // 3) out = att_h @ W_out  (fp32 out)
    f16_gemm_t<false><<<dim3(D_MODEL / 128, M_ROWS / 128), 128, smem_gemm>>>(
        ath, wo, out, nullptr, M_ROWS, D_MODEL, D_MODEL);
}